// round 6
// baseline (speedup 1.0000x reference)
#include <cuda_runtime.h>
#include <cuda_bf16.h>

#define B_ 8
#define C_ 192
#define N_ 16384
#define NH_ 6
#define HD_ 32

// Scratch (device globals: allocation-free per harness rules)
__device__ __nv_bfloat16 g_q[B_*C_*N_];
__device__ __nv_bfloat16 g_k[B_*C_*N_];
__device__ float g_v[B_*C_*N_];
__device__ float g_ssq[B_*C_];
__device__ float g_ssk[B_*C_];
__device__ float g_G[B_*NH_*HD_*HD_];
__device__ float g_M[B_*C_*C_];

__device__ __forceinline__ void fma2(unsigned long long& d, unsigned long long a,
                                     unsigned long long b, unsigned long long c) {
    asm("fma.rn.f32x2 %0, %1, %2, %3;" : "=l"(d) : "l"(a), "l"(b), "l"(c));
}
__device__ __forceinline__ float2 unpack2(unsigned long long v) {
    float2 f;
    f.x = __uint_as_float((unsigned int)(v & 0xffffffffull));
    f.y = __uint_as_float((unsigned int)(v >> 32));
    return f;
}

// ---------------------------------------------------------------------------
// K1: merged depthwise 3x3 conv. cin<128 -> bf16 q/k + per-channel ssq/ssk;
// cin>=128 -> fp32 v. Blocks (b==0, cin<48) also zero the gram accumulator.
// ---------------------------------------------------------------------------
__global__ __launch_bounds__(256) void conv_k(const float* __restrict__ x,
                                              const float* __restrict__ w,
                                              const float* __restrict__ bias) {
    const int RS = 132;
    extern __shared__ float tile[];
    int cin = blockIdx.x, b = blockIdx.y;
    if (b == 0 && cin < 48) {
        float* Gz = g_G + cin * 1024;
        for (int i = threadIdx.x; i < 1024; i += 256) Gz[i] = 0.f;
    }
    const float* xp = x + ((size_t)b * C_ + cin) * N_;
    for (int i = threadIdx.x; i < 130 * 130; i += 256) {
        int r = i / 130, c = i - r * 130;
        int yy = r - 1, xx = c - 1;
        float v = 0.f;
        if ((unsigned)yy < 128u && (unsigned)xx < 128u) v = xp[yy * 128 + xx];
        tile[r * RS + c] = v;
    }
    __syncthreads();

    int o0 = cin * 3;
    float w9[3][9], bs[3];
#pragma unroll
    for (int j = 0; j < 3; j++) {
        int o = o0 + j;
        bs[j] = bias[o];
#pragma unroll
        for (int t = 0; t < 9; t++) w9[j][t] = w[o * 9 + t];
    }

    if (cin < 128) {  // q/k path: bf16 store + sum of squares
        __nv_bfloat16* dst[3];
#pragma unroll
        for (int j = 0; j < 3; j++) {
            int o = o0 + j;
            if (o < C_) dst[j] = g_q + ((size_t)b * C_ + o) * N_;
            else        dst[j] = g_k + ((size_t)b * C_ + (o - C_)) * N_;
        }
        float ss0 = 0.f, ss1 = 0.f, ss2 = 0.f;
        for (int p = threadIdx.x; p < N_; p += 256) {
            int r = p >> 7, c = p & 127;
            float in9[9];
#pragma unroll
            for (int dy = 0; dy < 3; dy++)
#pragma unroll
                for (int dx = 0; dx < 3; dx++)
                    in9[dy * 3 + dx] = tile[(r + dy) * RS + (c + dx)];
#pragma unroll
            for (int j = 0; j < 3; j++) {
                float acc = bs[j];
#pragma unroll
                for (int t = 0; t < 9; t++) acc = fmaf(in9[t], w9[j][t], acc);
                __nv_bfloat16 bv = __float2bfloat16(acc);
                dst[j][p] = bv;
                float rv = __bfloat162float(bv);
                if (j == 0)      ss0 = fmaf(rv, rv, ss0);
                else if (j == 1) ss1 = fmaf(rv, rv, ss1);
                else             ss2 = fmaf(rv, rv, ss2);
            }
        }
        __shared__ float red[3][8];
        float s3[3] = {ss0, ss1, ss2};
#pragma unroll
        for (int j = 0; j < 3; j++) {
            float v = s3[j];
#pragma unroll
            for (int off = 16; off > 0; off >>= 1) v += __shfl_xor_sync(0xffffffffu, v, off);
            if ((threadIdx.x & 31) == 0) red[j][threadIdx.x >> 5] = v;
        }
        __syncthreads();
        if (threadIdx.x < 3) {
            float t = 0.f;
#pragma unroll
            for (int wd = 0; wd < 8; wd++) t += red[threadIdx.x][wd];
            int o = o0 + threadIdx.x;
            if (o < C_) g_ssq[b * C_ + o] = t;
            else        g_ssk[b * C_ + (o - C_)] = t;
        }
    } else {  // v path: fp32
        float* dst[3];
#pragma unroll
        for (int j = 0; j < 3; j++)
            dst[j] = g_v + ((size_t)b * C_ + (o0 + j - 2 * C_)) * N_;
        for (int p = threadIdx.x; p < N_; p += 256) {
            int r = p >> 7, c = p & 127;
            float in9[9];
#pragma unroll
            for (int dy = 0; dy < 3; dy++)
#pragma unroll
                for (int dx = 0; dx < 3; dx++)
                    in9[dy * 3 + dx] = tile[(r + dy) * RS + (c + dx)];
#pragma unroll
            for (int j = 0; j < 3; j++) {
                float acc = bs[j];
#pragma unroll
                for (int t = 0; t < 9; t++) acc = fmaf(in9[t], w9[j][t], acc);
                dst[j][p] = acc;
            }
        }
    }
}

// ---------------------------------------------------------------------------
// K2: raw gram G[b,h] += q_h @ k_h^T over an N-chunk of 1024 (bf16 in, fp32
// acc). 128 threads, 4 q-rows x 2 k-cols (tx, tx+16), float4 t-steps.
// ---------------------------------------------------------------------------
#define GSTR 68
__global__ __launch_bounds__(128) void gram_k() {
    int chunk = blockIdx.x, h = blockIdx.y, b = blockIdx.z;
    const __nv_bfloat16* qb = g_q + ((size_t)b * C_ + h * HD_) * N_;
    const __nv_bfloat16* kb = g_k + ((size_t)b * C_ + h * HD_) * N_;
    __shared__ float qs[HD_ * GSTR], ks[HD_ * GSTR];
    int tid = threadIdx.x;
    int tx = tid & 15, ty = tid >> 4;
    float acc[4][2];
#pragma unroll
    for (int j = 0; j < 4; j++) { acc[j][0] = 0.f; acc[j][1] = 0.f; }

    int n0 = chunk * 1024;
    for (int nb = 0; nb < 1024; nb += 64) {
        // fill 32x64 fp32 tiles from bf16 (uint2 = 4 bf16 per load)
#pragma unroll
        for (int i = 0; i < 4; i++) {
            int e = tid + i * 128;
            int cc = e >> 4, vt = (e & 15) << 2;
            uint2 qu = *(const uint2*)(qb + (size_t)cc * N_ + n0 + nb + vt);
            uint2 ku = *(const uint2*)(kb + (size_t)cc * N_ + n0 + nb + vt);
            float2 qa = __bfloat1622float2(*(__nv_bfloat162*)&qu.x);
            float2 qbf = __bfloat1622float2(*(__nv_bfloat162*)&qu.y);
            float2 ka = __bfloat1622float2(*(__nv_bfloat162*)&ku.x);
            float2 kbf = __bfloat1622float2(*(__nv_bfloat162*)&ku.y);
            *(float4*)&qs[cc * GSTR + vt] = make_float4(qa.x, qa.y, qbf.x, qbf.y);
            *(float4*)&ks[cc * GSTR + vt] = make_float4(ka.x, ka.y, kbf.x, kbf.y);
        }
        __syncthreads();
#pragma unroll 4
        for (int t = 0; t < 64; t += 4) {
            float4 k0 = *(const float4*)&ks[tx * GSTR + t];
            float4 k1 = *(const float4*)&ks[(tx + 16) * GSTR + t];
#pragma unroll
            for (int j = 0; j < 4; j++) {
                float4 qv = *(const float4*)&qs[(4 * ty + j) * GSTR + t];
                acc[j][0] = fmaf(qv.x, k0.x, fmaf(qv.y, k0.y,
                            fmaf(qv.z, k0.z, fmaf(qv.w, k0.w, acc[j][0]))));
                acc[j][1] = fmaf(qv.x, k1.x, fmaf(qv.y, k1.y,
                            fmaf(qv.z, k1.z, fmaf(qv.w, k1.w, acc[j][1]))));
            }
        }
        __syncthreads();
    }
    float* Gp = g_G + ((b * NH_ + h) << 10);
#pragma unroll
    for (int j = 0; j < 4; j++) {
        atomicAdd(&Gp[(4 * ty + j) * 32 + tx],      acc[j][0]);
        atomicAdd(&Gp[(4 * ty + j) * 32 + tx + 16], acc[j][1]);
    }
}

// ---------------------------------------------------------------------------
// K3: softmax (normalize by ||q||·||k||, temp) + compose
// M[b] rows o0..o0+31 = w_out @ blockdiag(attn heads). grid (6, B).
// ---------------------------------------------------------------------------
__global__ __launch_bounds__(256) void compose_k(const float* __restrict__ temp,
                                                 const float* __restrict__ w_out) {
    extern __shared__ float cs[];
    float* A   = cs;          // [6*32*32]
    float* Wsh = cs + 6144;   // [32*192]
    __shared__ float sinvsh[C_];
    int oc = blockIdx.x, b = blockIdx.y;
    int o0 = oc * 32;
    int tid = threadIdx.x;

    if (tid < C_)
        sinvsh[tid] = 1.f / fmaxf(sqrtf(g_ssk[b * C_ + tid]), 1e-12f);
    for (int i = tid; i < 32 * 192; i += 256) {
        int o = i / 192, c = i - o * 192;
        Wsh[i] = w_out[(o0 + o) * C_ + c];
    }
    __syncthreads();
    if (tid < C_) {
        int h = tid >> 5, cl = tid & 31;
        float nq = fmaxf(sqrtf(g_ssq[b * C_ + tid]), 1e-12f);
        float sc = temp[h] / nq;
        const float* Gr = g_G + ((b * NH_ + h) << 10) + cl * HD_;
        const float* si = sinvsh + h * HD_;
        float row[32], mx = -3.4e38f;
#pragma unroll
        for (int d = 0; d < 32; d++) {
            float v = Gr[d] * sc * si[d];
            row[d] = v;
            mx = fmaxf(mx, v);
        }
        float s = 0.f;
#pragma unroll
        for (int d = 0; d < 32; d++) { row[d] = expf(row[d] - mx); s += row[d]; }
        float inv = 1.f / s;
#pragma unroll
        for (int d = 0; d < 32; d++) A[h * 1024 + cl * 32 + d] = row[d] * inv;
    }
    __syncthreads();
    float* Mb = g_M + (size_t)b * C_ * C_ + (size_t)o0 * C_;
    for (int i = tid; i < 32 * 192; i += 256) {
        int o = i / 192, g = i - o * 192;
        int h = g >> 5, d = g & 31;
        const float* wr = Wsh + o * 192 + h * 32;
        const float* Ar = A + h * 1024 + d;
        float acc = 0.f;
#pragma unroll
        for (int cl = 0; cl < 32; cl++) acc = fmaf(wr[cl], Ar[cl * 32], acc);
        Mb[i] = acc;
    }
}

// ---------------------------------------------------------------------------
// K4: out[b] = M[b] @ v[b] + b_out. 96-row x 128-col CTA, 192 threads,
// 8x8 thread tile, all-f32x2 inner loop with ZERO pack movs:
//  - Ms k-major: LDS.128 as ulonglong2 -> row-pair packs
//  - Vs duplicated (v,v): LDS.128 as ulonglong2 -> broadcast packs
// V staged per 24-k chunk via register prefetch (single smem buffer).
// ---------------------------------------------------------------------------
#define KC 24
#define MSTR 100
#define VSTR 264
__global__ __launch_bounds__(192, 2) void gemm_out_k(const float* __restrict__ b_out,
                                                     float* __restrict__ out) {
    extern __shared__ float sm[];
    float* Ms  = sm;                 // [192][MSTR]: Ms[kk*MSTR + o], o<96
    float* Vs2 = sm + 192 * MSTR;    // [KC][VSTR]: dup cols
    int b = blockIdx.z;
    int o0 = blockIdx.y * 96;
    int n0 = blockIdx.x * 128;
    int tid = threadIdx.x;

    const float* Mg = g_M + (size_t)b * C_ * C_;
    const float* vb = g_v + (size_t)b * C_ * N_ + n0;

    // prefetch v chunk 0 into registers (4 float4 per thread)
    float4 pf[4];
#pragma unroll
    for (int j = 0; j < 4; j++) {
        int e = tid + j * 192;
        int kk = e >> 5, c = (e & 31) << 2;
        pf[j] = *(const float4*)(vb + (size_t)kk * N_ + c);
    }
    // stage M k-major (rows o0..o0+95)
#pragma unroll 4
    for (int j = 0; j < 24; j++) {
        int vi = tid + j * 192;
        int o = vi / 48, kv = vi % 48;
        float4 m4 = *(const float4*)(Mg + (size_t)(o0 + o) * C_ + 4 * kv);
        Ms[(4 * kv + 0) * MSTR + o] = m4.x;
        Ms[(4 * kv + 1) * MSTR + o] = m4.y;
        Ms[(4 * kv + 2) * MSTR + o] = m4.z;
        Ms[(4 * kv + 3) * MSTR + o] = m4.w;
    }

    int tx = tid & 15, ty = tid >> 4;   // 16 col-groups x 12 row-groups

    unsigned long long acc[4][8];
#pragma unroll
    for (int rp = 0; rp < 4; rp++)
#pragma unroll
        for (int p = 0; p < 8; p++) acc[rp][p] = 0ull;

    for (int ch = 0; ch < 8; ch++) {
        __syncthreads();
        // store dup chunk from prefetch regs
#pragma unroll
        for (int j = 0; j < 4; j++) {
            int e = tid + j * 192;
            int kk = e >> 5, c = (e & 31) << 2;
            float4 v = pf[j];
            float* dp = Vs2 + kk * VSTR + 2 * c;
            *(float4*)(dp)     = make_float4(v.x, v.x, v.y, v.y);
            *(float4*)(dp + 4) = make_float4(v.z, v.z, v.w, v.w);
        }
        if (ch < 7) {
#pragma unroll
            for (int j = 0; j < 4; j++) {
                int e = tid + j * 192;
                int kk = e >> 5, c = (e & 31) << 2;
                pf[j] = *(const float4*)(vb + (size_t)((ch + 1) * KC + kk) * N_ + c);
            }
        }
        __syncthreads();
        const float* Mc = Ms + ch * KC * MSTR;
#pragma unroll 4
        for (int kk = 0; kk < KC; kk++) {
            const float* vr = Vs2 + kk * VSTR + 4 * tx;
            ulonglong2 vp0 = *(const ulonglong2*)(vr);
            ulonglong2 vp1 = *(const ulonglong2*)(vr + 64);
            ulonglong2 vp2 = *(const ulonglong2*)(vr + 128);
            ulonglong2 vp3 = *(const ulonglong2*)(vr + 192);
            const float* mr = Mc + kk * MSTR + 8 * ty;
            ulonglong2 mp01 = *(const ulonglong2*)(mr);
            ulonglong2 mp23 = *(const ulonglong2*)(mr + 4);
            unsigned long long m0 = mp01.x, m1 = mp01.y, m2 = mp23.x, m3 = mp23.y;
            fma2(acc[0][0], m0, vp0.x, acc[0][0]); fma2(acc[0][1], m0, vp0.y, acc[0][1]);
            fma2(acc[0][2], m0, vp1.x, acc[0][2]); fma2(acc[0][3], m0, vp1.y, acc[0][3]);
            fma2(acc[0][4], m0, vp2.x, acc[0][4]); fma2(acc[0][5], m0, vp2.y, acc[0][5]);
            fma2(acc[0][6], m0, vp3.x, acc[0][6]); fma2(acc[0][7], m0, vp3.y, acc[0][7]);
            fma2(acc[1][0], m1, vp0.x, acc[1][0]); fma2(acc[1][1], m1, vp0.y, acc[1][1]);
            fma2(acc[1][2], m1, vp1.x, acc[1][2]); fma2(acc[1][3], m1, vp1.y, acc[1][3]);
            fma2(acc[1][4], m1, vp2.x, acc[1][4]); fma2(acc[1][5], m1, vp2.y, acc[1][5]);
            fma2(acc[1][6], m1, vp3.x, acc[1][6]); fma2(acc[1][7], m1, vp3.y, acc[1][7]);
            fma2(acc[2][0], m2, vp0.x, acc[2][0]); fma2(acc[2][1], m2, vp0.y, acc[2][1]);
            fma2(acc[2][2], m2, vp1.x, acc[2][2]); fma2(acc[2][3], m2, vp1.y, acc[2][3]);
            fma2(acc[2][4], m2, vp2.x, acc[2][4]); fma2(acc[2][5], m2, vp2.y, acc[2][5]);
            fma2(acc[2][6], m2, vp3.x, acc[2][6]); fma2(acc[2][7], m2, vp3.y, acc[2][7]);
            fma2(acc[3][0], m3, vp0.x, acc[3][0]); fma2(acc[3][1], m3, vp0.y, acc[3][1]);
            fma2(acc[3][2], m3, vp1.x, acc[3][2]); fma2(acc[3][3], m3, vp1.y, acc[3][3]);
            fma2(acc[3][4], m3, vp2.x, acc[3][4]); fma2(acc[3][5], m3, vp2.y, acc[3][5]);
            fma2(acc[3][6], m3, vp3.x, acc[3][6]); fma2(acc[3][7], m3, vp3.y, acc[3][7]);
        }
    }

    // epilogue: pack rp covers rows (8ty+2rp, 8ty+2rp+1); col pair p->(32g+2tx+{0,1})
#pragma unroll
    for (int rp = 0; rp < 4; rp++) {
        int r = o0 + 8 * ty + 2 * rp;
        float b0 = b_out[r], b1 = b_out[r + 1];
        float* op0 = out + ((size_t)b * C_ + r) * N_ + n0;
        float* op1 = op0 + N_;
#pragma unroll
        for (int g = 0; g < 4; g++) {
            float2 e0 = unpack2(acc[rp][2 * g]);
            float2 e1 = unpack2(acc[rp][2 * g + 1]);
            int col = 32 * g + 2 * tx;
            *(float2*)(op0 + col) = make_float2(e0.x + b0, e1.x + b0);
            *(float2*)(op1 + col) = make_float2(e0.y + b1, e1.y + b1);
        }
    }
}

// ---------------------------------------------------------------------------
extern "C" void kernel_launch(void* const* d_in, const int* in_sizes, int n_in,
                              void* d_out, int out_size) {
    const float* x     = (const float*)d_in[0];
    const float* w_qkv = (const float*)d_in[1];
    const float* b_qkv = (const float*)d_in[2];
    const float* temp  = (const float*)d_in[3];
    const float* w_out = (const float*)d_in[4];
    const float* b_out = (const float*)d_in[5];
    float* out = (float*)d_out;

    (void)in_sizes; (void)n_in; (void)out_size;

    static int inited = 0;
    const int conv_smem = 130 * 132 * 4;
    const int gemm_smem = (192 * MSTR + KC * VSTR) * 4;
    const int comp_smem = (6144 + 32 * 192) * 4;
    if (!inited) {
        cudaFuncSetAttribute(conv_k,     cudaFuncAttributeMaxDynamicSharedMemorySize, conv_smem);
        cudaFuncSetAttribute(gemm_out_k, cudaFuncAttributeMaxDynamicSharedMemorySize, gemm_smem);
        cudaFuncSetAttribute(compose_k,  cudaFuncAttributeMaxDynamicSharedMemorySize, comp_smem);
        inited = 1;
    }

    // 4 launches; profiled launch (idx 3) = gemm_out_k.
    conv_k<<<dim3(C_, B_), 256, conv_smem>>>(x, w_qkv, b_qkv);
    gram_k<<<dim3(16, NH_, B_), 128>>>();
    compose_k<<<dim3(6, B_), 256, comp_smem>>>(temp, w_out);
    gemm_out_k<<<dim3(N_ / 128, 2, B_), 192, gemm_smem>>>(b_out, out);
}

// round 8
// speedup vs baseline: 1.6836x; 1.6836x over previous
#include <cuda_runtime.h>
#include <cuda_bf16.h>

#define B_ 8
#define C_ 192
#define N_ 16384
#define NH_ 6
#define HD_ 32

// Scratch (device globals: allocation-free per harness rules)
__device__ __nv_bfloat16 g_q[B_*C_*N_];
__device__ __nv_bfloat16 g_k[B_*C_*N_];
__device__ float g_v[B_*C_*N_];
__device__ float g_ssq[B_*C_];
__device__ float g_ssk[B_*C_];
__device__ float g_G[B_*NH_*HD_*HD_];
__device__ float g_M[B_*C_*C_];

__device__ __forceinline__ unsigned tf32r(float x) {
    unsigned u;
    asm("cvt.rna.tf32.f32 %0, %1;" : "=r"(u) : "f"(x));
    return u;
}

// ---------------------------------------------------------------------------
// K1: merged depthwise 3x3 conv. cin<128 -> bf16 q/k + ssq/ssk; cin>=128 ->
// fp32 v. Blocks (b==0, cin<48) zero the gram accumulator.
// ---------------------------------------------------------------------------
__global__ __launch_bounds__(256) void conv_k(const float* __restrict__ x,
                                              const float* __restrict__ w,
                                              const float* __restrict__ bias) {
    const int RS = 132;
    extern __shared__ float tile[];
    int cin = blockIdx.x, b = blockIdx.y;
    if (b == 0 && cin < 48) {
        float* Gz = g_G + cin * 1024;
        for (int i = threadIdx.x; i < 1024; i += 256) Gz[i] = 0.f;
    }
    const float* xp = x + ((size_t)b * C_ + cin) * N_;
    for (int i = threadIdx.x; i < 130 * 130; i += 256) {
        int r = i / 130, c = i - r * 130;
        int yy = r - 1, xx = c - 1;
        float v = 0.f;
        if ((unsigned)yy < 128u && (unsigned)xx < 128u) v = xp[yy * 128 + xx];
        tile[r * RS + c] = v;
    }
    __syncthreads();

    int o0 = cin * 3;
    float w9[3][9], bs[3];
#pragma unroll
    for (int j = 0; j < 3; j++) {
        int o = o0 + j;
        bs[j] = bias[o];
#pragma unroll
        for (int t = 0; t < 9; t++) w9[j][t] = w[o * 9 + t];
    }

    if (cin < 128) {
        __nv_bfloat16* dst[3];
#pragma unroll
        for (int j = 0; j < 3; j++) {
            int o = o0 + j;
            if (o < C_) dst[j] = g_q + ((size_t)b * C_ + o) * N_;
            else        dst[j] = g_k + ((size_t)b * C_ + (o - C_)) * N_;
        }
        float ss0 = 0.f, ss1 = 0.f, ss2 = 0.f;
        for (int p = threadIdx.x; p < N_; p += 256) {
            int r = p >> 7, c = p & 127;
            float in9[9];
#pragma unroll
            for (int dy = 0; dy < 3; dy++)
#pragma unroll
                for (int dx = 0; dx < 3; dx++)
                    in9[dy * 3 + dx] = tile[(r + dy) * RS + (c + dx)];
#pragma unroll
            for (int j = 0; j < 3; j++) {
                float acc = bs[j];
#pragma unroll
                for (int t = 0; t < 9; t++) acc = fmaf(in9[t], w9[j][t], acc);
                __nv_bfloat16 bv = __float2bfloat16(acc);
                dst[j][p] = bv;
                float rv = __bfloat162float(bv);
                if (j == 0)      ss0 = fmaf(rv, rv, ss0);
                else if (j == 1) ss1 = fmaf(rv, rv, ss1);
                else             ss2 = fmaf(rv, rv, ss2);
            }
        }
        __shared__ float red[3][8];
        float s3[3] = {ss0, ss1, ss2};
#pragma unroll
        for (int j = 0; j < 3; j++) {
            float v = s3[j];
#pragma unroll
            for (int off = 16; off > 0; off >>= 1) v += __shfl_xor_sync(0xffffffffu, v, off);
            if ((threadIdx.x & 31) == 0) red[j][threadIdx.x >> 5] = v;
        }
        __syncthreads();
        if (threadIdx.x < 3) {
            float t = 0.f;
#pragma unroll
            for (int wd = 0; wd < 8; wd++) t += red[threadIdx.x][wd];
            int o = o0 + threadIdx.x;
            if (o < C_) g_ssq[b * C_ + o] = t;
            else        g_ssk[b * C_ + (o - C_)] = t;
        }
    } else {
        float* dst[3];
#pragma unroll
        for (int j = 0; j < 3; j++)
            dst[j] = g_v + ((size_t)b * C_ + (o0 + j - 2 * C_)) * N_;
        for (int p = threadIdx.x; p < N_; p += 256) {
            int r = p >> 7, c = p & 127;
            float in9[9];
#pragma unroll
            for (int dy = 0; dy < 3; dy++)
#pragma unroll
                for (int dx = 0; dx < 3; dx++)
                    in9[dy * 3 + dx] = tile[(r + dy) * RS + (c + dx)];
#pragma unroll
            for (int j = 0; j < 3; j++) {
                float acc = bs[j];
#pragma unroll
                for (int t = 0; t < 9; t++) acc = fmaf(in9[t], w9[j][t], acc);
                dst[j][p] = acc;
            }
        }
    }
}

// ---------------------------------------------------------------------------
// K2: raw gram G[b,h] += q_h @ k_h^T over N-chunks of 1024 (bf16, fp32 acc).
// ---------------------------------------------------------------------------
#define GSTR 68
__global__ __launch_bounds__(128) void gram_k() {
    int chunk = blockIdx.x, h = blockIdx.y, b = blockIdx.z;
    const __nv_bfloat16* qb = g_q + ((size_t)b * C_ + h * HD_) * N_;
    const __nv_bfloat16* kb = g_k + ((size_t)b * C_ + h * HD_) * N_;
    __shared__ float qs[HD_ * GSTR], ks[HD_ * GSTR];
    int tid = threadIdx.x;
    int tx = tid & 15, ty = tid >> 4;
    float acc[4][2];
#pragma unroll
    for (int j = 0; j < 4; j++) { acc[j][0] = 0.f; acc[j][1] = 0.f; }

    int n0 = chunk * 1024;
    for (int nb = 0; nb < 1024; nb += 64) {
#pragma unroll
        for (int i = 0; i < 4; i++) {
            int e = tid + i * 128;
            int cc = e >> 4, vt = (e & 15) << 2;
            uint2 qu = *(const uint2*)(qb + (size_t)cc * N_ + n0 + nb + vt);
            uint2 ku = *(const uint2*)(kb + (size_t)cc * N_ + n0 + nb + vt);
            float2 qa = __bfloat1622float2(*(__nv_bfloat162*)&qu.x);
            float2 qbf = __bfloat1622float2(*(__nv_bfloat162*)&qu.y);
            float2 ka = __bfloat1622float2(*(__nv_bfloat162*)&ku.x);
            float2 kbf = __bfloat1622float2(*(__nv_bfloat162*)&ku.y);
            *(float4*)&qs[cc * GSTR + vt] = make_float4(qa.x, qa.y, qbf.x, qbf.y);
            *(float4*)&ks[cc * GSTR + vt] = make_float4(ka.x, ka.y, kbf.x, kbf.y);
        }
        __syncthreads();
#pragma unroll 4
        for (int t = 0; t < 64; t += 4) {
            float4 k0 = *(const float4*)&ks[tx * GSTR + t];
            float4 k1 = *(const float4*)&ks[(tx + 16) * GSTR + t];
#pragma unroll
            for (int j = 0; j < 4; j++) {
                float4 qv = *(const float4*)&qs[(4 * ty + j) * GSTR + t];
                acc[j][0] = fmaf(qv.x, k0.x, fmaf(qv.y, k0.y,
                            fmaf(qv.z, k0.z, fmaf(qv.w, k0.w, acc[j][0]))));
                acc[j][1] = fmaf(qv.x, k1.x, fmaf(qv.y, k1.y,
                            fmaf(qv.z, k1.z, fmaf(qv.w, k1.w, acc[j][1]))));
            }
        }
        __syncthreads();
    }
    float* Gp = g_G + ((b * NH_ + h) << 10);
#pragma unroll
    for (int j = 0; j < 4; j++) {
        atomicAdd(&Gp[(4 * ty + j) * 32 + tx],      acc[j][0]);
        atomicAdd(&Gp[(4 * ty + j) * 32 + tx + 16], acc[j][1]);
    }
}

// ---------------------------------------------------------------------------
// K3: softmax + compose M[b] = w_out @ blockdiag(attn heads). grid (6, B).
// ---------------------------------------------------------------------------
__global__ __launch_bounds__(256) void compose_k(const float* __restrict__ temp,
                                                 const float* __restrict__ w_out) {
    extern __shared__ float cs[];
    float* A   = cs;          // [6*32*32]
    float* Wsh = cs + 6144;   // [32*192]
    __shared__ float sinvsh[C_];
    int oc = blockIdx.x, b = blockIdx.y;
    int o0 = oc * 32;
    int tid = threadIdx.x;

    if (tid < C_)
        sinvsh[tid] = 1.f / fmaxf(sqrtf(g_ssk[b * C_ + tid]), 1e-12f);
    for (int i = tid; i < 32 * 192; i += 256) {
        int o = i / 192, c = i - o * 192;
        Wsh[i] = w_out[(o0 + o) * C_ + c];
    }
    __syncthreads();
    if (tid < C_) {
        int h = tid >> 5, cl = tid & 31;
        float nq = fmaxf(sqrtf(g_ssq[b * C_ + tid]), 1e-12f);
        float sc = temp[h] / nq;
        const float* Gr = g_G + ((b * NH_ + h) << 10) + cl * HD_;
        const float* si = sinvsh + h * HD_;
        float row[32], mx = -3.4e38f;
#pragma unroll
        for (int d = 0; d < 32; d++) {
            float v = Gr[d] * sc * si[d];
            row[d] = v;
            mx = fmaxf(mx, v);
        }
        float s = 0.f;
#pragma unroll
        for (int d = 0; d < 32; d++) { row[d] = expf(row[d] - mx); s += row[d]; }
        float inv = 1.f / s;
#pragma unroll
        for (int d = 0; d < 32; d++) A[h * 1024 + cl * 32 + d] = row[d] * inv;
    }
    __syncthreads();
    float* Mb = g_M + (size_t)b * C_ * C_ + (size_t)o0 * C_;
    for (int i = tid; i < 32 * 192; i += 256) {
        int o = i / 192, g = i - o * 192;
        int h = g >> 5, d = g & 31;
        const float* wr = Wsh + o * 192 + h * 32;
        const float* Ar = A + h * 1024 + d;
        float acc = 0.f;
#pragma unroll
        for (int cl = 0; cl < 32; cl++) acc = fmaf(wr[cl], Ar[cl * 32], acc);
        Mb[i] = acc;
    }
}

// ---------------------------------------------------------------------------
// K4: out[b] = M[b](192x192) @ v[b](192xN) + b_out via mma.sync tf32
// (m16n8k8, sm_80-class PTX -> legacy HMMA on sm_103 tensor pipe).
// 12 warps; warp w owns rows 16w..16w+15; A-fragments (24 k-steps) in regs.
// B: [192k x 64n] f32->tf32 smem tile, double-buffered; 16 stages of n=64.
// ---------------------------------------------------------------------------
#define BSTR 68
#define BBUF (192 * BSTR)
#define GEMM_SMEM (2 * BBUF * 4)

__device__ __forceinline__ void mma_tf32(float& c0, float& c1, float& c2, float& c3,
                                         unsigned a0, unsigned a1, unsigned a2, unsigned a3,
                                         unsigned b0, unsigned b1) {
    asm volatile(
        "mma.sync.aligned.m16n8k8.row.col.f32.tf32.tf32.f32 "
        "{%0,%1,%2,%3}, {%4,%5,%6,%7}, {%8,%9}, {%0,%1,%2,%3};"
        : "+f"(c0), "+f"(c1), "+f"(c2), "+f"(c3)
        : "r"(a0), "r"(a1), "r"(a2), "r"(a3), "r"(b0), "r"(b1));
}

__global__ __launch_bounds__(384, 1) void gemm_out_k(const float* __restrict__ b_out,
                                                     float* __restrict__ out) {
    extern __shared__ unsigned Bs[];   // [2][192][BSTR] tf32
    int tid = threadIdx.x, wid = tid >> 5, lid = tid & 31;
    int b = blockIdx.y;
    int n0 = blockIdx.x * 1024;

    const float* Mg = g_M + (size_t)b * C_ * C_;
    const float* vb = g_v + (size_t)b * C_ * N_ + n0;

    // ---- A fragments in registers: warp owns rows 16*wid .. +15 ----
    int g = lid >> 2, t = lid & 3;
    int r0 = 16 * wid + g, r1 = r0 + 8;
    unsigned af[24][4];
#pragma unroll
    for (int j = 0; j < 24; j++) {
        af[j][0] = tf32r(Mg[(size_t)r0 * C_ + 8 * j + t]);
        af[j][1] = tf32r(Mg[(size_t)r1 * C_ + 8 * j + t]);
        af[j][2] = tf32r(Mg[(size_t)r0 * C_ + 8 * j + 4 + t]);
        af[j][3] = tf32r(Mg[(size_t)r1 * C_ + 8 * j + 4 + t]);
    }
    float bias_lo = b_out[r0], bias_hi = b_out[r1];

    // stage 0 -> buffer 0  (thread e: row = e/16, 4 cols at (e%16)*4)
    {
        int row = tid >> 4, c4 = (tid & 15) << 2;
#pragma unroll
        for (int i = 0; i < 8; i++) {
            int kk = row + i * 24;
            float4 v = *(const float4*)(vb + (size_t)kk * N_ + c4);
            unsigned* dp = Bs + kk * BSTR + c4;
            dp[0] = tf32r(v.x); dp[1] = tf32r(v.y);
            dp[2] = tf32r(v.z); dp[3] = tf32r(v.w);
        }
    }
    __syncthreads();

    for (int s = 0; s < 16; s++) {
        float4 pf[8];
        if (s < 15) {
            int row = tid >> 4, c4 = (tid & 15) << 2;
#pragma unroll
            for (int i = 0; i < 8; i++) {
                int kk = row + i * 24;
                pf[i] = *(const float4*)(vb + (size_t)kk * N_ + (s + 1) * 64 + c4);
            }
        }
        const unsigned* Bc = Bs + (s & 1) * BBUF;
        // compute: 8 n8-blocks
#pragma unroll
        for (int nb = 0; nb < 8; nb++) {
            float c0 = bias_lo, c1 = bias_lo, c2 = bias_hi, c3 = bias_hi;
            const unsigned* bp = Bc + 8 * nb + (lid >> 2) + (lid & 3) * BSTR;
#pragma unroll
            for (int j = 0; j < 24; j++) {
                unsigned b0 = bp[8 * j * BSTR];
                unsigned b1 = bp[(8 * j + 4) * BSTR];
                mma_tf32(c0, c1, c2, c3, af[j][0], af[j][1], af[j][2], af[j][3], b0, b1);
            }
            int col = n0 + s * 64 + 8 * nb + 2 * (lid & 3);
            *(float2*)(out + (size_t)(b * C_ + r0) * N_ + col) = make_float2(c0, c1);
            *(float2*)(out + (size_t)(b * C_ + r1) * N_ + col) = make_float2(c2, c3);
        }
        __syncthreads();
        if (s < 15) {
            int row = tid >> 4, c4 = (tid & 15) << 2;
            unsigned* Bn = Bs + ((s + 1) & 1) * BBUF;
#pragma unroll
            for (int i = 0; i < 8; i++) {
                int kk = row + i * 24;
                unsigned* dp = Bn + kk * BSTR + c4;
                dp[0] = tf32r(pf[i].x); dp[1] = tf32r(pf[i].y);
                dp[2] = tf32r(pf[i].z); dp[3] = tf32r(pf[i].w);
            }
            __syncthreads();
        }
    }
}

// ---------------------------------------------------------------------------
extern "C" void kernel_launch(void* const* d_in, const int* in_sizes, int n_in,
                              void* d_out, int out_size) {
    const float* x     = (const float*)d_in[0];
    const float* w_qkv = (const float*)d_in[1];
    const float* b_qkv = (const float*)d_in[2];
    const float* temp  = (const float*)d_in[3];
    const float* w_out = (const float*)d_in[4];
    const float* b_out = (const float*)d_in[5];
    float* out = (float*)d_out;

    (void)in_sizes; (void)n_in; (void)out_size;

    static int inited = 0;
    const int conv_smem = 130 * 132 * 4;
    const int comp_smem = (6144 + 32 * 192) * 4;
    if (!inited) {
        cudaFuncSetAttribute(conv_k,     cudaFuncAttributeMaxDynamicSharedMemorySize, conv_smem);
        cudaFuncSetAttribute(compose_k,  cudaFuncAttributeMaxDynamicSharedMemorySize, comp_smem);
        cudaFuncSetAttribute(gemm_out_k, cudaFuncAttributeMaxDynamicSharedMemorySize, GEMM_SMEM);
        inited = 1;
    }

    // 4 launches; profiled launch (idx 3) = mma.sync gemm_out_k.
    conv_k<<<dim3(C_, B_), 256, conv_smem>>>(x, w_qkv, b_qkv);
    gram_k<<<dim3(16, NH_, B_), 128>>>();
    compose_k<<<dim3(6, B_), 256, comp_smem>>>(temp, w_out);
    gemm_out_k<<<dim3(N_ / 1024, B_), 384, GEMM_SMEM>>>(b_out, out);
}

// round 10
// speedup vs baseline: 2.1929x; 1.3025x over previous
#include <cuda_runtime.h>
#include <cuda_bf16.h>

#define B_ 8
#define C_ 192
#define N_ 16384
#define NH_ 6
#define HD_ 32

// Scratch (device globals: allocation-free per harness rules)
__device__ __nv_bfloat16 g_q[B_*C_*N_];
__device__ __nv_bfloat16 g_k[B_*C_*N_];
__device__ float g_v[B_*C_*N_];
__device__ float g_ssq[B_*C_];
__device__ float g_ssk[B_*C_];
__device__ float g_G[B_*NH_*HD_*HD_];
__device__ float g_M[B_*C_*C_];

__device__ __forceinline__ unsigned tf32r(float x) {
    unsigned u;
    asm("cvt.rna.tf32.f32 %0, %1;" : "=r"(u) : "f"(x));
    return u;
}
__device__ __forceinline__ unsigned su32(const void* p) {
    unsigned r;
    asm("{ .reg .u64 t; cvta.to.shared.u64 t, %1; cvt.u32.u64 %0, t; }"
        : "=r"(r) : "l"(p));
    return r;
}
#define CP_ASYNC16(s, g) asm volatile("cp.async.ca.shared.global [%0], [%1], 16;" :: "r"(s), "l"(g))
#define CP_COMMIT()      asm volatile("cp.async.commit_group;")
#define CP_WAIT(n)       asm volatile("cp.async.wait_group %0;" :: "n"(n))

__device__ __forceinline__ void ldsm_x4(unsigned& r0, unsigned& r1, unsigned& r2,
                                        unsigned& r3, unsigned addr) {
    asm volatile("ldmatrix.sync.aligned.m8n8.x4.shared.b16 {%0,%1,%2,%3}, [%4];"
                 : "=r"(r0), "=r"(r1), "=r"(r2), "=r"(r3) : "r"(addr));
}
__device__ __forceinline__ void ldsm_x2(unsigned& r0, unsigned& r1, unsigned addr) {
    asm volatile("ldmatrix.sync.aligned.m8n8.x2.shared.b16 {%0,%1}, [%2];"
                 : "=r"(r0), "=r"(r1) : "r"(addr));
}
__device__ __forceinline__ void mma_bf16(float& c0, float& c1, float& c2, float& c3,
                                         unsigned a0, unsigned a1, unsigned a2, unsigned a3,
                                         unsigned b0, unsigned b1) {
    asm volatile(
        "mma.sync.aligned.m16n8k16.row.col.f32.bf16.bf16.f32 "
        "{%0,%1,%2,%3}, {%4,%5,%6,%7}, {%8,%9}, {%0,%1,%2,%3};"
        : "+f"(c0), "+f"(c1), "+f"(c2), "+f"(c3)
        : "r"(a0), "r"(a1), "r"(a2), "r"(a3), "r"(b0), "r"(b1));
}

// ---------------------------------------------------------------------------
// K1: merged depthwise 3x3 conv. cin<128 -> bf16 q/k + ssq/ssk; cin>=128 ->
// fp32 v. Blocks (b==0, cin<48) zero the gram accumulator.
// ---------------------------------------------------------------------------
__global__ __launch_bounds__(256) void conv_k(const float* __restrict__ x,
                                              const float* __restrict__ w,
                                              const float* __restrict__ bias) {
    const int RS = 132;
    extern __shared__ float tile[];
    int cin = blockIdx.x, b = blockIdx.y;
    if (b == 0 && cin < 48) {
        float* Gz = g_G + cin * 1024;
        for (int i = threadIdx.x; i < 1024; i += 256) Gz[i] = 0.f;
    }
    const float* xp = x + ((size_t)b * C_ + cin) * N_;
    for (int i = threadIdx.x; i < 130 * 130; i += 256) {
        int r = i / 130, c = i - r * 130;
        int yy = r - 1, xx = c - 1;
        float v = 0.f;
        if ((unsigned)yy < 128u && (unsigned)xx < 128u) v = xp[yy * 128 + xx];
        tile[r * RS + c] = v;
    }
    __syncthreads();

    int o0 = cin * 3;
    float w9[3][9], bs[3];
#pragma unroll
    for (int j = 0; j < 3; j++) {
        int o = o0 + j;
        bs[j] = bias[o];
#pragma unroll
        for (int t = 0; t < 9; t++) w9[j][t] = w[o * 9 + t];
    }

    if (cin < 128) {
        __nv_bfloat16* dst[3];
#pragma unroll
        for (int j = 0; j < 3; j++) {
            int o = o0 + j;
            if (o < C_) dst[j] = g_q + ((size_t)b * C_ + o) * N_;
            else        dst[j] = g_k + ((size_t)b * C_ + (o - C_)) * N_;
        }
        float ss0 = 0.f, ss1 = 0.f, ss2 = 0.f;
        for (int p = threadIdx.x; p < N_; p += 256) {
            int r = p >> 7, c = p & 127;
            float in9[9];
#pragma unroll
            for (int dy = 0; dy < 3; dy++)
#pragma unroll
                for (int dx = 0; dx < 3; dx++)
                    in9[dy * 3 + dx] = tile[(r + dy) * RS + (c + dx)];
#pragma unroll
            for (int j = 0; j < 3; j++) {
                float acc = bs[j];
#pragma unroll
                for (int t = 0; t < 9; t++) acc = fmaf(in9[t], w9[j][t], acc);
                __nv_bfloat16 bv = __float2bfloat16(acc);
                dst[j][p] = bv;
                float rv = __bfloat162float(bv);
                if (j == 0)      ss0 = fmaf(rv, rv, ss0);
                else if (j == 1) ss1 = fmaf(rv, rv, ss1);
                else             ss2 = fmaf(rv, rv, ss2);
            }
        }
        __shared__ float red[3][8];
        float s3[3] = {ss0, ss1, ss2};
#pragma unroll
        for (int j = 0; j < 3; j++) {
            float v = s3[j];
#pragma unroll
            for (int off = 16; off > 0; off >>= 1) v += __shfl_xor_sync(0xffffffffu, v, off);
            if ((threadIdx.x & 31) == 0) red[j][threadIdx.x >> 5] = v;
        }
        __syncthreads();
        if (threadIdx.x < 3) {
            float t = 0.f;
#pragma unroll
            for (int wd = 0; wd < 8; wd++) t += red[threadIdx.x][wd];
            int o = o0 + threadIdx.x;
            if (o < C_) g_ssq[b * C_ + o] = t;
            else        g_ssk[b * C_ + (o - C_)] = t;
        }
    } else {
        float* dst[3];
#pragma unroll
        for (int j = 0; j < 3; j++)
            dst[j] = g_v + ((size_t)b * C_ + (o0 + j - 2 * C_)) * N_;
        for (int p = threadIdx.x; p < N_; p += 256) {
            int r = p >> 7, c = p & 127;
            float in9[9];
#pragma unroll
            for (int dy = 0; dy < 3; dy++)
#pragma unroll
                for (int dx = 0; dx < 3; dx++)
                    in9[dy * 3 + dx] = tile[(r + dy) * RS + (c + dx)];
#pragma unroll
            for (int j = 0; j < 3; j++) {
                float acc = bs[j];
#pragma unroll
                for (int t = 0; t < 9; t++) acc = fmaf(in9[t], w9[j][t], acc);
                dst[j][p] = acc;
            }
        }
    }
}

// ---------------------------------------------------------------------------
// K2: gram G[b,h] += q_h @ k_h^T via mma.sync bf16 (m16n8k16) + ldmatrix.
// A = q [m=ch][k=sp] row-major -> ldmatrix.x4 (non-trans).
// B = k [n=ch][k=sp]: consecutive contraction values are contiguous at fixed
// n, which IS the mma B fragment -> ldmatrix.x2 NON-trans (rows = n).
// cp.async double-buffered; final chunk must CP_WAIT(0).
// ---------------------------------------------------------------------------
#define GROW 272                       // bytes per channel row (256 + 16 pad)
#define GARR (32 * GROW)               // one 32x128 bf16 tile = 8704 B
#define GBUF (2 * GARR)                // q + k
#define GRAM_SMEM (2 * GBUF)           // double buffer = 34816 B

__global__ __launch_bounds__(128) void gram_k() {
    extern __shared__ char gsm[];
    unsigned smem_base = su32(gsm);
    int chunk = blockIdx.x, h = blockIdx.y, b = blockIdx.z;
    const __nv_bfloat16* qb = g_q + ((size_t)b * C_ + h * HD_) * N_;
    const __nv_bfloat16* kb = g_k + ((size_t)b * C_ + h * HD_) * N_;
    int tid = threadIdx.x, wid = tid >> 5, lane = tid & 31;
    int n0 = chunk * 1024;

    int mt = wid & 1;            // q-channel m-tile (16 rows)
    int nb0 = (wid >> 1) * 2;    // k-channel n8 pair

    auto stage = [&](int sub, int buf) {
        unsigned dstq = smem_base + buf * GBUF;
        unsigned dstk = dstq + GARR;
        int r = tid >> 4, s16 = tid & 15;
#pragma unroll
        for (int i = 0; i < 4; i++) {
            int row = r + i * 8;
            const __nv_bfloat16* sq = qb + (size_t)row * N_ + n0 + sub * 128 + s16 * 8;
            const __nv_bfloat16* sk = kb + (size_t)row * N_ + n0 + sub * 128 + s16 * 8;
            CP_ASYNC16(dstq + row * GROW + s16 * 16, sq);
            CP_ASYNC16(dstk + row * GROW + s16 * 16, sk);
        }
        CP_COMMIT();
    };

    stage(0, 0);

    float acc[2][4];
#pragma unroll
    for (int nbi = 0; nbi < 2; nbi++)
#pragma unroll
        for (int p = 0; p < 4; p++) acc[nbi][p] = 0.f;

    unsigned a_off = (lane & 15) * GROW + (lane >> 4) * 16;
    unsigned b_off = (lane & 7) * GROW + ((lane >> 3) & 1) * 16;

    for (int sub = 0; sub < 8; sub++) {
        int buf = sub & 1;
        if (sub < 7) { stage(sub + 1, buf ^ 1); CP_WAIT(1); }
        else         { CP_WAIT(0); }
        __syncthreads();
        unsigned qs = smem_base + buf * GBUF + mt * 16 * GROW;
        unsigned ks = smem_base + buf * GBUF + GARR;
#pragma unroll
        for (int ksix = 0; ksix < 8; ksix++) {
            unsigned a0, a1, a2, a3;
            ldsm_x4(a0, a1, a2, a3, qs + a_off + ksix * 32);
#pragma unroll
            for (int nbi = 0; nbi < 2; nbi++) {
                unsigned b0, b1;
                ldsm_x2(b0, b1, ks + (nb0 + nbi) * 8 * GROW + b_off + ksix * 32);
                mma_bf16(acc[nbi][0], acc[nbi][1], acc[nbi][2], acc[nbi][3],
                         a0, a1, a2, a3, b0, b1);
            }
        }
        __syncthreads();
    }

    float* Gp = g_G + ((b * NH_ + h) << 10);
    int row = lane >> 2, colp = 2 * (lane & 3);
#pragma unroll
    for (int nbi = 0; nbi < 2; nbi++) {
        int cbase = (nb0 + nbi) * 8 + colp;
        atomicAdd(&Gp[(mt * 16 + row) * 32 + cbase],         acc[nbi][0]);
        atomicAdd(&Gp[(mt * 16 + row) * 32 + cbase + 1],     acc[nbi][1]);
        atomicAdd(&Gp[(mt * 16 + row + 8) * 32 + cbase],     acc[nbi][2]);
        atomicAdd(&Gp[(mt * 16 + row + 8) * 32 + cbase + 1], acc[nbi][3]);
    }
}

// ---------------------------------------------------------------------------
// K3: softmax + compose M[b] = w_out @ blockdiag(attn heads). grid (6, B).
// ---------------------------------------------------------------------------
__global__ __launch_bounds__(256) void compose_k(const float* __restrict__ temp,
                                                 const float* __restrict__ w_out) {
    extern __shared__ float cs[];
    float* A   = cs;          // [6*32*32]
    float* Wsh = cs + 6144;   // [32*192]
    __shared__ float sinvsh[C_];
    int oc = blockIdx.x, b = blockIdx.y;
    int o0 = oc * 32;
    int tid = threadIdx.x;

    if (tid < C_)
        sinvsh[tid] = 1.f / fmaxf(sqrtf(g_ssk[b * C_ + tid]), 1e-12f);
    for (int i = tid; i < 32 * 192; i += 256) {
        int o = i / 192, c = i - o * 192;
        Wsh[i] = w_out[(o0 + o) * C_ + c];
    }
    __syncthreads();
    if (tid < C_) {
        int h = tid >> 5, cl = tid & 31;
        float nq = fmaxf(sqrtf(g_ssq[b * C_ + tid]), 1e-12f);
        float sc = temp[h] / nq;
        const float* Gr = g_G + ((b * NH_ + h) << 10) + cl * HD_;
        const float* si = sinvsh + h * HD_;
        float row[32], mx = -3.4e38f;
#pragma unroll
        for (int d = 0; d < 32; d++) {
            float v = Gr[d] * sc * si[d];
            row[d] = v;
            mx = fmaxf(mx, v);
        }
        float s = 0.f;
#pragma unroll
        for (int d = 0; d < 32; d++) { row[d] = expf(row[d] - mx); s += row[d]; }
        float inv = 1.f / s;
#pragma unroll
        for (int d = 0; d < 32; d++) A[h * 1024 + cl * 32 + d] = row[d] * inv;
    }
    __syncthreads();
    float* Mb = g_M + (size_t)b * C_ * C_ + (size_t)o0 * C_;
    for (int i = tid; i < 32 * 192; i += 256) {
        int o = i / 192, g = i - o * 192;
        int h = g >> 5, d = g & 31;
        const float* wr = Wsh + o * 192 + h * 32;
        const float* Ar = A + h * 1024 + d;
        float acc = 0.f;
#pragma unroll
        for (int cl = 0; cl < 32; cl++) acc = fmaf(wr[cl], Ar[cl * 32], acc);
        Mb[i] = acc;
    }
}

// ---------------------------------------------------------------------------
// K4: out[b] = M[b](192x192) @ v[b](192xN) + b_out via mma.sync tf32
// (m16n8k8). 12 warps; warp w owns rows 16w..16w+15; A-fragments in regs.
// B: [192k x 64n] f32->tf32 smem tile (stride 72: conflict-free fragment
// reads), double-buffered; 16 stages of n=64.
// ---------------------------------------------------------------------------
#define BSTR 72
#define BBUF (192 * BSTR)
#define GEMM_SMEM (2 * BBUF * 4)

__device__ __forceinline__ void mma_tf32(float& c0, float& c1, float& c2, float& c3,
                                         unsigned a0, unsigned a1, unsigned a2, unsigned a3,
                                         unsigned b0, unsigned b1) {
    asm volatile(
        "mma.sync.aligned.m16n8k8.row.col.f32.tf32.tf32.f32 "
        "{%0,%1,%2,%3}, {%4,%5,%6,%7}, {%8,%9}, {%0,%1,%2,%3};"
        : "+f"(c0), "+f"(c1), "+f"(c2), "+f"(c3)
        : "r"(a0), "r"(a1), "r"(a2), "r"(a3), "r"(b0), "r"(b1));
}

__global__ __launch_bounds__(384, 1) void gemm_out_k(const float* __restrict__ b_out,
                                                     float* __restrict__ out) {
    extern __shared__ unsigned Bs[];   // [2][192][BSTR] tf32
    int tid = threadIdx.x, wid = tid >> 5, lid = tid & 31;
    int b = blockIdx.y;
    int n0 = blockIdx.x * 1024;

    const float* Mg = g_M + (size_t)b * C_ * C_;
    const float* vb = g_v + (size_t)b * C_ * N_ + n0;

    // ---- A fragments in registers: warp owns rows 16*wid .. +15 ----
    int g = lid >> 2, t = lid & 3;
    int r0 = 16 * wid + g, r1 = r0 + 8;
    unsigned af[24][4];
#pragma unroll
    for (int j = 0; j < 24; j++) {
        af[j][0] = tf32r(Mg[(size_t)r0 * C_ + 8 * j + t]);
        af[j][1] = tf32r(Mg[(size_t)r1 * C_ + 8 * j + t]);
        af[j][2] = tf32r(Mg[(size_t)r0 * C_ + 8 * j + 4 + t]);
        af[j][3] = tf32r(Mg[(size_t)r1 * C_ + 8 * j + 4 + t]);
    }
    float bias_lo = b_out[r0], bias_hi = b_out[r1];

    // stage 0 -> buffer 0  (thread e: row = e/16, 4 cols at (e%16)*4)
    {
        int row = tid >> 4, c4 = (tid & 15) << 2;
#pragma unroll
        for (int i = 0; i < 8; i++) {
            int kk = row + i * 24;
            float4 v = *(const float4*)(vb + (size_t)kk * N_ + c4);
            unsigned* dp = Bs + kk * BSTR + c4;
            dp[0] = tf32r(v.x); dp[1] = tf32r(v.y);
            dp[2] = tf32r(v.z); dp[3] = tf32r(v.w);
        }
    }
    __syncthreads();

    for (int s = 0; s < 16; s++) {
        float4 pf[8];
        if (s < 15) {
            int row = tid >> 4, c4 = (tid & 15) << 2;
#pragma unroll
            for (int i = 0; i < 8; i++) {
                int kk = row + i * 24;
                pf[i] = *(const float4*)(vb + (size_t)kk * N_ + (s + 1) * 64 + c4);
            }
        }
        const unsigned* Bc = Bs + (s & 1) * BBUF;
        // compute: 8 n8-blocks
#pragma unroll
        for (int nb = 0; nb < 8; nb++) {
            float c0 = bias_lo, c1 = bias_lo, c2 = bias_hi, c3 = bias_hi;
            const unsigned* bp = Bc + 8 * nb + (lid >> 2) + (lid & 3) * BSTR;
#pragma unroll
            for (int j = 0; j < 24; j++) {
                unsigned b0 = bp[8 * j * BSTR];
                unsigned b1 = bp[(8 * j + 4) * BSTR];
                mma_tf32(c0, c1, c2, c3, af[j][0], af[j][1], af[j][2], af[j][3], b0, b1);
            }
            int col = n0 + s * 64 + 8 * nb + 2 * (lid & 3);
            *(float2*)(out + (size_t)(b * C_ + r0) * N_ + col) = make_float2(c0, c1);
            *(float2*)(out + (size_t)(b * C_ + r1) * N_ + col) = make_float2(c2, c3);
        }
        __syncthreads();
        if (s < 15) {
            int row = tid >> 4, c4 = (tid & 15) << 2;
            unsigned* Bn = Bs + ((s + 1) & 1) * BBUF;
#pragma unroll
            for (int i = 0; i < 8; i++) {
                int kk = row + i * 24;
                unsigned* dp = Bn + kk * BSTR + c4;
                dp[0] = tf32r(pf[i].x); dp[1] = tf32r(pf[i].y);
                dp[2] = tf32r(pf[i].z); dp[3] = tf32r(pf[i].w);
            }
            __syncthreads();
        }
    }
}

// ---------------------------------------------------------------------------
extern "C" void kernel_launch(void* const* d_in, const int* in_sizes, int n_in,
                              void* d_out, int out_size) {
    const float* x     = (const float*)d_in[0];
    const float* w_qkv = (const float*)d_in[1];
    const float* b_qkv = (const float*)d_in[2];
    const float* temp  = (const float*)d_in[3];
    const float* w_out = (const float*)d_in[4];
    const float* b_out = (const float*)d_in[5];
    float* out = (float*)d_out;

    (void)in_sizes; (void)n_in; (void)out_size;

    static int inited = 0;
    const int conv_smem = 130 * 132 * 4;
    const int comp_smem = (6144 + 32 * 192) * 4;
    if (!inited) {
        cudaFuncSetAttribute(conv_k,     cudaFuncAttributeMaxDynamicSharedMemorySize, conv_smem);
        cudaFuncSetAttribute(gram_k,     cudaFuncAttributeMaxDynamicSharedMemorySize, GRAM_SMEM);
        cudaFuncSetAttribute(compose_k,  cudaFuncAttributeMaxDynamicSharedMemorySize, comp_smem);
        cudaFuncSetAttribute(gemm_out_k, cudaFuncAttributeMaxDynamicSharedMemorySize, GEMM_SMEM);
        inited = 1;
    }

    // 4 launches; profiled launch (idx 3) = gemm_out_k (verify conflict fix).
    conv_k<<<dim3(C_, B_), 256, conv_smem>>>(x, w_qkv, b_qkv);
    gram_k<<<dim3(16, NH_, B_), 128, GRAM_SMEM>>>();
    compose_k<<<dim3(6, B_), 256, comp_smem>>>(temp, w_out);
    gemm_out_k<<<dim3(N_ / 1024, B_), 384, GEMM_SMEM>>>(b_out, out);
}

// round 11
// speedup vs baseline: 2.2496x; 1.0259x over previous
#include <cuda_runtime.h>
#include <cuda_bf16.h>

#define B_ 8
#define C_ 192
#define N_ 16384
#define NH_ 6
#define HD_ 32

// Scratch (device globals: allocation-free per harness rules)
__device__ __nv_bfloat16 g_q[B_*C_*N_];
__device__ __nv_bfloat16 g_k[B_*C_*N_];
__device__ float g_v[B_*C_*N_];
__device__ float g_ssq[2*B_*C_];   // two half-plane partials
__device__ float g_ssk[2*B_*C_];
__device__ float g_G[B_*NH_*HD_*HD_];
__device__ float g_M[B_*C_*C_];

__device__ __forceinline__ unsigned tf32r(float x) {
    unsigned u;
    asm("cvt.rna.tf32.f32 %0, %1;" : "=r"(u) : "f"(x));
    return u;
}
__device__ __forceinline__ unsigned su32(const void* p) {
    unsigned r;
    asm("{ .reg .u64 t; cvta.to.shared.u64 t, %1; cvt.u32.u64 %0, t; }"
        : "=r"(r) : "l"(p));
    return r;
}
#define CP_ASYNC16(s, g) asm volatile("cp.async.ca.shared.global [%0], [%1], 16;" :: "r"(s), "l"(g))
#define CP_COMMIT()      asm volatile("cp.async.commit_group;")
#define CP_WAIT(n)       asm volatile("cp.async.wait_group %0;" :: "n"(n))

__device__ __forceinline__ void ldsm_x4(unsigned& r0, unsigned& r1, unsigned& r2,
                                        unsigned& r3, unsigned addr) {
    asm volatile("ldmatrix.sync.aligned.m8n8.x4.shared.b16 {%0,%1,%2,%3}, [%4];"
                 : "=r"(r0), "=r"(r1), "=r"(r2), "=r"(r3) : "r"(addr));
}
__device__ __forceinline__ void ldsm_x2(unsigned& r0, unsigned& r1, unsigned addr) {
    asm volatile("ldmatrix.sync.aligned.m8n8.x2.shared.b16 {%0,%1}, [%2];"
                 : "=r"(r0), "=r"(r1) : "r"(addr));
}
__device__ __forceinline__ void mma_bf16(float& c0, float& c1, float& c2, float& c3,
                                         unsigned a0, unsigned a1, unsigned a2, unsigned a3,
                                         unsigned b0, unsigned b1) {
    asm volatile(
        "mma.sync.aligned.m16n8k16.row.col.f32.bf16.bf16.f32 "
        "{%0,%1,%2,%3}, {%4,%5,%6,%7}, {%8,%9}, {%0,%1,%2,%3};"
        : "+f"(c0), "+f"(c1), "+f"(c2), "+f"(c3)
        : "r"(a0), "r"(a1), "r"(a2), "r"(a3), "r"(b0), "r"(b1));
}

// ---------------------------------------------------------------------------
// K0: no-op shims (profiling alignment: ncu captures the 4th launch).
// ---------------------------------------------------------------------------
__global__ void nop_k() {}

// ---------------------------------------------------------------------------
// K1: depthwise 3x3 conv, HALF-PLANE blocks (64 rows + halo; smem 34.8KB ->
// 6 CTAs/SM). cin<128 -> bf16 q/k + per-half ssq/ssk partials; cin>=128 ->
// fp32 v. Blocks (b==0, half==0, cin<48) zero the gram accumulator.
// ---------------------------------------------------------------------------
__global__ __launch_bounds__(256) void conv_k(const float* __restrict__ x,
                                              const float* __restrict__ w,
                                              const float* __restrict__ bias) {
    const int RS = 132;
    extern __shared__ float tile[];    // [66][132]
    int cin = blockIdx.x, half = blockIdx.y, b = blockIdx.z;
    if (b == 0 && half == 0 && cin < 48) {
        float* Gz = g_G + cin * 1024;
        for (int i = threadIdx.x; i < 1024; i += 256) Gz[i] = 0.f;
    }
    int r0 = half * 64;
    const float* xp = x + ((size_t)b * C_ + cin) * N_;
    for (int i = threadIdx.x; i < 66 * 130; i += 256) {
        int rr = i / 130, c = i - rr * 130;
        int yy = r0 + rr - 1, xx = c - 1;
        float v = 0.f;
        if ((unsigned)yy < 128u && (unsigned)xx < 128u) v = xp[yy * 128 + xx];
        tile[rr * RS + c] = v;
    }
    __syncthreads();

    int o0 = cin * 3;
    float w9[3][9], bs[3];
#pragma unroll
    for (int j = 0; j < 3; j++) {
        int o = o0 + j;
        bs[j] = bias[o];
#pragma unroll
        for (int t = 0; t < 9; t++) w9[j][t] = w[o * 9 + t];
    }
    size_t hoff = (size_t)r0 * 128;

    if (cin < 128) {
        __nv_bfloat16* dst[3];
#pragma unroll
        for (int j = 0; j < 3; j++) {
            int o = o0 + j;
            if (o < C_) dst[j] = g_q + ((size_t)b * C_ + o) * N_ + hoff;
            else        dst[j] = g_k + ((size_t)b * C_ + (o - C_)) * N_ + hoff;
        }
        float ss0 = 0.f, ss1 = 0.f, ss2 = 0.f;
        for (int p = threadIdx.x; p < 8192; p += 256) {
            int r = p >> 7, c = p & 127;
            float in9[9];
#pragma unroll
            for (int dy = 0; dy < 3; dy++)
#pragma unroll
                for (int dx = 0; dx < 3; dx++)
                    in9[dy * 3 + dx] = tile[(r + dy) * RS + (c + dx)];
#pragma unroll
            for (int j = 0; j < 3; j++) {
                float acc = bs[j];
#pragma unroll
                for (int t = 0; t < 9; t++) acc = fmaf(in9[t], w9[j][t], acc);
                __nv_bfloat16 bv = __float2bfloat16(acc);
                dst[j][p] = bv;
                float rv = __bfloat162float(bv);
                if (j == 0)      ss0 = fmaf(rv, rv, ss0);
                else if (j == 1) ss1 = fmaf(rv, rv, ss1);
                else             ss2 = fmaf(rv, rv, ss2);
            }
        }
        __shared__ float red[3][8];
        float s3[3] = {ss0, ss1, ss2};
#pragma unroll
        for (int j = 0; j < 3; j++) {
            float v = s3[j];
#pragma unroll
            for (int off = 16; off > 0; off >>= 1) v += __shfl_xor_sync(0xffffffffu, v, off);
            if ((threadIdx.x & 31) == 0) red[j][threadIdx.x >> 5] = v;
        }
        __syncthreads();
        if (threadIdx.x < 3) {
            float t = 0.f;
#pragma unroll
            for (int wd = 0; wd < 8; wd++) t += red[threadIdx.x][wd];
            int o = o0 + threadIdx.x;
            int part = half * B_ * C_;
            if (o < C_) g_ssq[part + b * C_ + o] = t;
            else        g_ssk[part + b * C_ + (o - C_)] = t;
        }
    } else {
        float* dst[3];
#pragma unroll
        for (int j = 0; j < 3; j++)
            dst[j] = g_v + ((size_t)b * C_ + (o0 + j - 2 * C_)) * N_ + hoff;
        for (int p = threadIdx.x; p < 8192; p += 256) {
            int r = p >> 7, c = p & 127;
            float in9[9];
#pragma unroll
            for (int dy = 0; dy < 3; dy++)
#pragma unroll
                for (int dx = 0; dx < 3; dx++)
                    in9[dy * 3 + dx] = tile[(r + dy) * RS + (c + dx)];
#pragma unroll
            for (int j = 0; j < 3; j++) {
                float acc = bs[j];
#pragma unroll
                for (int t = 0; t < 9; t++) acc = fmaf(in9[t], w9[j][t], acc);
                dst[j][p] = acc;
            }
        }
    }
}

// ---------------------------------------------------------------------------
// K2: gram G[b,h] += q_h @ k_h^T via mma.sync bf16 (m16n8k16) + ldmatrix.
// ---------------------------------------------------------------------------
#define GROW 272
#define GARR (32 * GROW)
#define GBUF (2 * GARR)
#define GRAM_SMEM (2 * GBUF)

__global__ __launch_bounds__(128) void gram_k() {
    extern __shared__ char gsm[];
    unsigned smem_base = su32(gsm);
    int chunk = blockIdx.x, h = blockIdx.y, b = blockIdx.z;
    const __nv_bfloat16* qb = g_q + ((size_t)b * C_ + h * HD_) * N_;
    const __nv_bfloat16* kb = g_k + ((size_t)b * C_ + h * HD_) * N_;
    int tid = threadIdx.x, wid = tid >> 5, lane = tid & 31;
    int n0 = chunk * 1024;

    int mt = wid & 1;
    int nb0 = (wid >> 1) * 2;

    auto stage = [&](int sub, int buf) {
        unsigned dstq = smem_base + buf * GBUF;
        unsigned dstk = dstq + GARR;
        int r = tid >> 4, s16 = tid & 15;
#pragma unroll
        for (int i = 0; i < 4; i++) {
            int row = r + i * 8;
            const __nv_bfloat16* sq = qb + (size_t)row * N_ + n0 + sub * 128 + s16 * 8;
            const __nv_bfloat16* sk = kb + (size_t)row * N_ + n0 + sub * 128 + s16 * 8;
            CP_ASYNC16(dstq + row * GROW + s16 * 16, sq);
            CP_ASYNC16(dstk + row * GROW + s16 * 16, sk);
        }
        CP_COMMIT();
    };

    stage(0, 0);

    float acc[2][4];
#pragma unroll
    for (int nbi = 0; nbi < 2; nbi++)
#pragma unroll
        for (int p = 0; p < 4; p++) acc[nbi][p] = 0.f;

    unsigned a_off = (lane & 15) * GROW + (lane >> 4) * 16;
    unsigned b_off = (lane & 7) * GROW + ((lane >> 3) & 1) * 16;

    for (int sub = 0; sub < 8; sub++) {
        int buf = sub & 1;
        if (sub < 7) { stage(sub + 1, buf ^ 1); CP_WAIT(1); }
        else         { CP_WAIT(0); }
        __syncthreads();
        unsigned qs = smem_base + buf * GBUF + mt * 16 * GROW;
        unsigned ks = smem_base + buf * GBUF + GARR;
#pragma unroll
        for (int ksix = 0; ksix < 8; ksix++) {
            unsigned a0, a1, a2, a3;
            ldsm_x4(a0, a1, a2, a3, qs + a_off + ksix * 32);
#pragma unroll
            for (int nbi = 0; nbi < 2; nbi++) {
                unsigned b0, b1;
                ldsm_x2(b0, b1, ks + (nb0 + nbi) * 8 * GROW + b_off + ksix * 32);
                mma_bf16(acc[nbi][0], acc[nbi][1], acc[nbi][2], acc[nbi][3],
                         a0, a1, a2, a3, b0, b1);
            }
        }
        __syncthreads();
    }

    float* Gp = g_G + ((b * NH_ + h) << 10);
    int row = lane >> 2, colp = 2 * (lane & 3);
#pragma unroll
    for (int nbi = 0; nbi < 2; nbi++) {
        int cbase = (nb0 + nbi) * 8 + colp;
        atomicAdd(&Gp[(mt * 16 + row) * 32 + cbase],         acc[nbi][0]);
        atomicAdd(&Gp[(mt * 16 + row) * 32 + cbase + 1],     acc[nbi][1]);
        atomicAdd(&Gp[(mt * 16 + row + 8) * 32 + cbase],     acc[nbi][2]);
        atomicAdd(&Gp[(mt * 16 + row + 8) * 32 + cbase + 1], acc[nbi][3]);
    }
}

// ---------------------------------------------------------------------------
// K3: softmax + compose M[b] = w_out @ blockdiag(attn heads). grid (6, B).
// ssq/ssk are the sum of the two conv half-plane partials.
// ---------------------------------------------------------------------------
__global__ __launch_bounds__(256) void compose_k(const float* __restrict__ temp,
                                                 const float* __restrict__ w_out) {
    extern __shared__ float cs[];
    float* A   = cs;          // [6*32*32]
    float* Wsh = cs + 6144;   // [32*192]
    __shared__ float sinvsh[C_];
    int oc = blockIdx.x, b = blockIdx.y;
    int o0 = oc * 32;
    int tid = threadIdx.x;

    if (tid < C_) {
        float sk = g_ssk[b * C_ + tid] + g_ssk[B_ * C_ + b * C_ + tid];
        sinvsh[tid] = 1.f / fmaxf(sqrtf(sk), 1e-12f);
    }
    for (int i = tid; i < 32 * 192; i += 256) {
        int o = i / 192, c = i - o * 192;
        Wsh[i] = w_out[(o0 + o) * C_ + c];
    }
    __syncthreads();
    if (tid < C_) {
        int h = tid >> 5, cl = tid & 31;
        float sq = g_ssq[b * C_ + tid] + g_ssq[B_ * C_ + b * C_ + tid];
        float nq = fmaxf(sqrtf(sq), 1e-12f);
        float sc = temp[h] / nq;
        const float* Gr = g_G + ((b * NH_ + h) << 10) + cl * HD_;
        const float* si = sinvsh + h * HD_;
        float row[32], mx = -3.4e38f;
#pragma unroll
        for (int d = 0; d < 32; d++) {
            float v = Gr[d] * sc * si[d];
            row[d] = v;
            mx = fmaxf(mx, v);
        }
        float s = 0.f;
#pragma unroll
        for (int d = 0; d < 32; d++) { row[d] = expf(row[d] - mx); s += row[d]; }
        float inv = 1.f / s;
#pragma unroll
        for (int d = 0; d < 32; d++) A[h * 1024 + cl * 32 + d] = row[d] * inv;
    }
    __syncthreads();
    float* Mb = g_M + (size_t)b * C_ * C_ + (size_t)o0 * C_;
    for (int i = tid; i < 32 * 192; i += 256) {
        int o = i / 192, g = i - o * 192;
        int h = g >> 5, d = g & 31;
        const float* wr = Wsh + o * 192 + h * 32;
        const float* Ar = A + h * 1024 + d;
        float acc = 0.f;
#pragma unroll
        for (int cl = 0; cl < 32; cl++) acc = fmaf(wr[cl], Ar[cl * 32], acc);
        Mb[i] = acc;
    }
}

// ---------------------------------------------------------------------------
// K4: out[b] = M[b](192x192) @ v[b](192xN) + b_out via mma.sync tf32
// (m16n8k8). 12 warps; warp w owns rows 16w..16w+15; A-fragments in regs.
// B: [192k x 64n] f32->tf32 smem tile (stride 72, conflict-free), double-
// buffered; 16 stages of n=64.  (unchanged from round 10)
// ---------------------------------------------------------------------------
#define BSTR 72
#define BBUF (192 * BSTR)
#define GEMM_SMEM (2 * BBUF * 4)

__device__ __forceinline__ void mma_tf32(float& c0, float& c1, float& c2, float& c3,
                                         unsigned a0, unsigned a1, unsigned a2, unsigned a3,
                                         unsigned b0, unsigned b1) {
    asm volatile(
        "mma.sync.aligned.m16n8k8.row.col.f32.tf32.tf32.f32 "
        "{%0,%1,%2,%3}, {%4,%5,%6,%7}, {%8,%9}, {%0,%1,%2,%3};"
        : "+f"(c0), "+f"(c1), "+f"(c2), "+f"(c3)
        : "r"(a0), "r"(a1), "r"(a2), "r"(a3), "r"(b0), "r"(b1));
}

__global__ __launch_bounds__(384, 1) void gemm_out_k(const float* __restrict__ b_out,
                                                     float* __restrict__ out) {
    extern __shared__ unsigned Bs[];   // [2][192][BSTR] tf32
    int tid = threadIdx.x, wid = tid >> 5, lid = tid & 31;
    int b = blockIdx.y;
    int n0 = blockIdx.x * 1024;

    const float* Mg = g_M + (size_t)b * C_ * C_;
    const float* vb = g_v + (size_t)b * C_ * N_ + n0;

    int g = lid >> 2, t = lid & 3;
    int r0 = 16 * wid + g, r1 = r0 + 8;
    unsigned af[24][4];
#pragma unroll
    for (int j = 0; j < 24; j++) {
        af[j][0] = tf32r(Mg[(size_t)r0 * C_ + 8 * j + t]);
        af[j][1] = tf32r(Mg[(size_t)r1 * C_ + 8 * j + t]);
        af[j][2] = tf32r(Mg[(size_t)r0 * C_ + 8 * j + 4 + t]);
        af[j][3] = tf32r(Mg[(size_t)r1 * C_ + 8 * j + 4 + t]);
    }
    float bias_lo = b_out[r0], bias_hi = b_out[r1];

    {
        int row = tid >> 4, c4 = (tid & 15) << 2;
#pragma unroll
        for (int i = 0; i < 8; i++) {
            int kk = row + i * 24;
            float4 v = *(const float4*)(vb + (size_t)kk * N_ + c4);
            unsigned* dp = Bs + kk * BSTR + c4;
            dp[0] = tf32r(v.x); dp[1] = tf32r(v.y);
            dp[2] = tf32r(v.z); dp[3] = tf32r(v.w);
        }
    }
    __syncthreads();

    for (int s = 0; s < 16; s++) {
        float4 pf[8];
        if (s < 15) {
            int row = tid >> 4, c4 = (tid & 15) << 2;
#pragma unroll
            for (int i = 0; i < 8; i++) {
                int kk = row + i * 24;
                pf[i] = *(const float4*)(vb + (size_t)kk * N_ + (s + 1) * 64 + c4);
            }
        }
        const unsigned* Bc = Bs + (s & 1) * BBUF;
#pragma unroll
        for (int nb = 0; nb < 8; nb++) {
            float c0 = bias_lo, c1 = bias_lo, c2 = bias_hi, c3 = bias_hi;
            const unsigned* bp = Bc + 8 * nb + (lid >> 2) + (lid & 3) * BSTR;
#pragma unroll
            for (int j = 0; j < 24; j++) {
                unsigned b0 = bp[8 * j * BSTR];
                unsigned b1 = bp[(8 * j + 4) * BSTR];
                mma_tf32(c0, c1, c2, c3, af[j][0], af[j][1], af[j][2], af[j][3], b0, b1);
            }
            int col = n0 + s * 64 + 8 * nb + 2 * (lid & 3);
            *(float2*)(out + (size_t)(b * C_ + r0) * N_ + col) = make_float2(c0, c1);
            *(float2*)(out + (size_t)(b * C_ + r1) * N_ + col) = make_float2(c2, c3);
        }
        __syncthreads();
        if (s < 15) {
            int row = tid >> 4, c4 = (tid & 15) << 2;
            unsigned* Bn = Bs + ((s + 1) & 1) * BBUF;
#pragma unroll
            for (int i = 0; i < 8; i++) {
                int kk = row + i * 24;
                unsigned* dp = Bn + kk * BSTR + c4;
                dp[0] = tf32r(pf[i].x); dp[1] = tf32r(pf[i].y);
                dp[2] = tf32r(pf[i].z); dp[3] = tf32r(pf[i].w);
            }
            __syncthreads();
        }
    }
}

// ---------------------------------------------------------------------------
extern "C" void kernel_launch(void* const* d_in, const int* in_sizes, int n_in,
                              void* d_out, int out_size) {
    const float* x     = (const float*)d_in[0];
    const float* w_qkv = (const float*)d_in[1];
    const float* b_qkv = (const float*)d_in[2];
    const float* temp  = (const float*)d_in[3];
    const float* w_out = (const float*)d_in[4];
    const float* b_out = (const float*)d_in[5];
    float* out = (float*)d_out;

    (void)in_sizes; (void)n_in; (void)out_size;

    static int inited = 0;
    const int conv_smem = 66 * 132 * 4;
    const int comp_smem = (6144 + 32 * 192) * 4;
    if (!inited) {
        cudaFuncSetAttribute(conv_k,     cudaFuncAttributeMaxDynamicSharedMemorySize, conv_smem);
        cudaFuncSetAttribute(gram_k,     cudaFuncAttributeMaxDynamicSharedMemorySize, GRAM_SMEM);
        cudaFuncSetAttribute(compose_k,  cudaFuncAttributeMaxDynamicSharedMemorySize, comp_smem);
        cudaFuncSetAttribute(gemm_out_k, cudaFuncAttributeMaxDynamicSharedMemorySize, GEMM_SMEM);
        inited = 1;
    }

    // 7 launches; profiled launch (idx 3) = conv_k this round.
    nop_k<<<1, 32>>>();
    nop_k<<<1, 32>>>();
    nop_k<<<1, 32>>>();
    conv_k<<<dim3(C_, 2, B_), 256, conv_smem>>>(x, w_qkv, b_qkv);
    gram_k<<<dim3(16, NH_, B_), 128, GRAM_SMEM>>>();
    compose_k<<<dim3(6, B_), 256, comp_smem>>>(temp, w_out);
    gemm_out_k<<<dim3(N_ / 1024, B_), 384, GEMM_SMEM>>>(b_out, out);
}

// round 12
// speedup vs baseline: 2.5451x; 1.1313x over previous
#include <cuda_runtime.h>
#include <cuda_bf16.h>

#define B_ 8
#define C_ 192
#define N_ 16384
#define NH_ 6
#define HD_ 32

// Scratch (device globals: allocation-free per harness rules)
__device__ __nv_bfloat16 g_q[B_*C_*N_];
__device__ __nv_bfloat16 g_k[B_*C_*N_];
__device__ float g_v[B_*C_*N_];
__device__ float g_ssq[2*B_*C_];   // two half-plane partials
__device__ float g_ssk[2*B_*C_];
__device__ float g_G[B_*NH_*HD_*HD_];
__device__ float g_M[B_*C_*C_];

__device__ __forceinline__ unsigned tf32r(float x) {
    unsigned u;
    asm("cvt.rna.tf32.f32 %0, %1;" : "=r"(u) : "f"(x));
    return u;
}
__device__ __forceinline__ unsigned su32(const void* p) {
    unsigned r;
    asm("{ .reg .u64 t; cvta.to.shared.u64 t, %1; cvt.u32.u64 %0, t; }"
        : "=r"(r) : "l"(p));
    return r;
}
// pack (lo=a, hi=b) into one bf16x2 word
__device__ __forceinline__ unsigned bf2(float lo, float hi) {
    unsigned r;
    asm("cvt.rn.bf16x2.f32 %0, %1, %2;" : "=r"(r) : "f"(hi), "f"(lo));
    return r;
}
#define CP_ASYNC16(s, g) asm volatile("cp.async.ca.shared.global [%0], [%1], 16;" :: "r"(s), "l"(g))
#define CP_COMMIT()      asm volatile("cp.async.commit_group;")
#define CP_WAIT(n)       asm volatile("cp.async.wait_group %0;" :: "n"(n))

__device__ __forceinline__ void ldsm_x4(unsigned& r0, unsigned& r1, unsigned& r2,
                                        unsigned& r3, unsigned addr) {
    asm volatile("ldmatrix.sync.aligned.m8n8.x4.shared.b16 {%0,%1,%2,%3}, [%4];"
                 : "=r"(r0), "=r"(r1), "=r"(r2), "=r"(r3) : "r"(addr));
}
__device__ __forceinline__ void ldsm_x2(unsigned& r0, unsigned& r1, unsigned addr) {
    asm volatile("ldmatrix.sync.aligned.m8n8.x2.shared.b16 {%0,%1}, [%2];"
                 : "=r"(r0), "=r"(r1) : "r"(addr));
}
__device__ __forceinline__ void mma_bf16(float& c0, float& c1, float& c2, float& c3,
                                         unsigned a0, unsigned a1, unsigned a2, unsigned a3,
                                         unsigned b0, unsigned b1) {
    asm volatile(
        "mma.sync.aligned.m16n8k16.row.col.f32.bf16.bf16.f32 "
        "{%0,%1,%2,%3}, {%4,%5,%6,%7}, {%8,%9}, {%0,%1,%2,%3};"
        : "+f"(c0), "+f"(c1), "+f"(c2), "+f"(c3)
        : "r"(a0), "r"(a1), "r"(a2), "r"(a3), "r"(b0), "r"(b1));
}

// ---------------------------------------------------------------------------
// K0: no-op shims (profiling alignment: ncu captures the 4th launch).
// ---------------------------------------------------------------------------
__global__ void nop_k() {}

// ---------------------------------------------------------------------------
// K1: depthwise 3x3 conv, half-plane blocks. Instruction-lean version:
//  - fill loop: warp-per-row / lane-per-col, no div/mod
//  - compute: 4-pixel quads, float4+float2 tap loads, packed bf16x2 /
//    float4 stores
// cin<128 -> bf16 q/k + per-half ssq/ssk partials; cin>=128 -> fp32 v.
// Blocks (b==0, half==0, cin<48) zero the gram accumulator.
// ---------------------------------------------------------------------------
__global__ __launch_bounds__(256) void conv_k(const float* __restrict__ x,
                                              const float* __restrict__ w,
                                              const float* __restrict__ bias) {
    const int RS = 132;
    extern __shared__ float tile[];    // [66][132]
    int cin = blockIdx.x, half = blockIdx.y, b = blockIdx.z;
    int tid = threadIdx.x, wid = tid >> 5, lane = tid & 31;
    if (b == 0 && half == 0 && cin < 48) {
        float* Gz = g_G + cin * 1024;
        for (int i = tid; i < 1024; i += 256) Gz[i] = 0.f;
    }
    int r0 = half * 64;
    const float* xp = x + ((size_t)b * C_ + cin) * N_;
    // fill: 66 rows x 130 cols (tile col c = gmem col c-1)
    for (int rr = wid; rr < 66; rr += 8) {
        int yy = r0 + rr - 1;
        bool rowok = (unsigned)yy < 128u;
        const float* rp = xp + yy * 128 - 1;
        float* tp = tile + rr * RS;
#pragma unroll
        for (int c = lane; c < 130; c += 32) {
            float v = 0.f;
            if (rowok && c >= 1 && c <= 128) v = rp[c];
            tp[c] = v;
        }
    }
    __syncthreads();

    int o0 = cin * 3;
    float w9[3][9], bs[3];
#pragma unroll
    for (int j = 0; j < 3; j++) {
        int o = o0 + j;
        bs[j] = bias[o];
#pragma unroll
        for (int t = 0; t < 9; t++) w9[j][t] = w[o * 9 + t];
    }
    size_t hoff = (size_t)r0 * 128;

    if (cin < 128) {
        __nv_bfloat16* dst[3];
#pragma unroll
        for (int j = 0; j < 3; j++) {
            int o = o0 + j;
            if (o < C_) dst[j] = g_q + ((size_t)b * C_ + o) * N_ + hoff;
            else        dst[j] = g_k + ((size_t)b * C_ + (o - C_)) * N_ + hoff;
        }
        float ss[3] = {0.f, 0.f, 0.f};
#pragma unroll
        for (int q = 0; q < 8; q++) {
            int p4 = tid + q * 256;
            int r = p4 >> 5, cc = (p4 & 31) << 2;
            const float* trow = tile + r * RS + cc;
            float xr[3][6];
#pragma unroll
            for (int dy = 0; dy < 3; dy++) {
                float4 f = *(const float4*)(trow + dy * RS);
                float2 g2 = *(const float2*)(trow + dy * RS + 4);
                xr[dy][0] = f.x; xr[dy][1] = f.y; xr[dy][2] = f.z;
                xr[dy][3] = f.w; xr[dy][4] = g2.x; xr[dy][5] = g2.y;
            }
#pragma unroll
            for (int j = 0; j < 3; j++) {
                float a[4];
#pragma unroll
                for (int i = 0; i < 4; i++) {
                    float acc = bs[j];
#pragma unroll
                    for (int dy = 0; dy < 3; dy++)
#pragma unroll
                        for (int dx = 0; dx < 3; dx++)
                            acc = fmaf(xr[dy][i + dx], w9[j][dy * 3 + dx], acc);
                    a[i] = acc;
                }
                ss[j] = fmaf(a[0], a[0], fmaf(a[1], a[1],
                         fmaf(a[2], a[2], fmaf(a[3], a[3], ss[j]))));
                uint2 pk = make_uint2(bf2(a[0], a[1]), bf2(a[2], a[3]));
                *(uint2*)(dst[j] + p4 * 4) = pk;
            }
        }
        __shared__ float red[3][8];
#pragma unroll
        for (int j = 0; j < 3; j++) {
            float v = ss[j];
#pragma unroll
            for (int off = 16; off > 0; off >>= 1) v += __shfl_xor_sync(0xffffffffu, v, off);
            if (lane == 0) red[j][wid] = v;
        }
        __syncthreads();
        if (tid < 3) {
            float t = 0.f;
#pragma unroll
            for (int wd = 0; wd < 8; wd++) t += red[tid][wd];
            int o = o0 + tid;
            int part = half * B_ * C_;
            if (o < C_) g_ssq[part + b * C_ + o] = t;
            else        g_ssk[part + b * C_ + (o - C_)] = t;
        }
    } else {
        float* dst[3];
#pragma unroll
        for (int j = 0; j < 3; j++)
            dst[j] = g_v + ((size_t)b * C_ + (o0 + j - 2 * C_)) * N_ + hoff;
#pragma unroll
        for (int q = 0; q < 8; q++) {
            int p4 = tid + q * 256;
            int r = p4 >> 5, cc = (p4 & 31) << 2;
            const float* trow = tile + r * RS + cc;
            float xr[3][6];
#pragma unroll
            for (int dy = 0; dy < 3; dy++) {
                float4 f = *(const float4*)(trow + dy * RS);
                float2 g2 = *(const float2*)(trow + dy * RS + 4);
                xr[dy][0] = f.x; xr[dy][1] = f.y; xr[dy][2] = f.z;
                xr[dy][3] = f.w; xr[dy][4] = g2.x; xr[dy][5] = g2.y;
            }
#pragma unroll
            for (int j = 0; j < 3; j++) {
                float a[4];
#pragma unroll
                for (int i = 0; i < 4; i++) {
                    float acc = bs[j];
#pragma unroll
                    for (int dy = 0; dy < 3; dy++)
#pragma unroll
                        for (int dx = 0; dx < 3; dx++)
                            acc = fmaf(xr[dy][i + dx], w9[j][dy * 3 + dx], acc);
                    a[i] = acc;
                }
                *(float4*)(dst[j] + p4 * 4) = make_float4(a[0], a[1], a[2], a[3]);
            }
        }
    }
}

// ---------------------------------------------------------------------------
// K2: gram G[b,h] += q_h @ k_h^T via mma.sync bf16 (m16n8k16) + ldmatrix.
// ---------------------------------------------------------------------------
#define GROW 272
#define GARR (32 * GROW)
#define GBUF (2 * GARR)
#define GRAM_SMEM (2 * GBUF)

__global__ __launch_bounds__(128) void gram_k() {
    extern __shared__ char gsm[];
    unsigned smem_base = su32(gsm);
    int chunk = blockIdx.x, h = blockIdx.y, b = blockIdx.z;
    const __nv_bfloat16* qb = g_q + ((size_t)b * C_ + h * HD_) * N_;
    const __nv_bfloat16* kb = g_k + ((size_t)b * C_ + h * HD_) * N_;
    int tid = threadIdx.x, wid = tid >> 5, lane = tid & 31;
    int n0 = chunk * 1024;

    int mt = wid & 1;
    int nb0 = (wid >> 1) * 2;

    auto stage = [&](int sub, int buf) {
        unsigned dstq = smem_base + buf * GBUF;
        unsigned dstk = dstq + GARR;
        int r = tid >> 4, s16 = tid & 15;
#pragma unroll
        for (int i = 0; i < 4; i++) {
            int row = r + i * 8;
            const __nv_bfloat16* sq = qb + (size_t)row * N_ + n0 + sub * 128 + s16 * 8;
            const __nv_bfloat16* sk = kb + (size_t)row * N_ + n0 + sub * 128 + s16 * 8;
            CP_ASYNC16(dstq + row * GROW + s16 * 16, sq);
            CP_ASYNC16(dstk + row * GROW + s16 * 16, sk);
        }
        CP_COMMIT();
    };

    stage(0, 0);

    float acc[2][4];
#pragma unroll
    for (int nbi = 0; nbi < 2; nbi++)
#pragma unroll
        for (int p = 0; p < 4; p++) acc[nbi][p] = 0.f;

    unsigned a_off = (lane & 15) * GROW + (lane >> 4) * 16;
    unsigned b_off = (lane & 7) * GROW + ((lane >> 3) & 1) * 16;

    for (int sub = 0; sub < 8; sub++) {
        int buf = sub & 1;
        if (sub < 7) { stage(sub + 1, buf ^ 1); CP_WAIT(1); }
        else         { CP_WAIT(0); }
        __syncthreads();
        unsigned qs = smem_base + buf * GBUF + mt * 16 * GROW;
        unsigned ks = smem_base + buf * GBUF + GARR;
#pragma unroll
        for (int ksix = 0; ksix < 8; ksix++) {
            unsigned a0, a1, a2, a3;
            ldsm_x4(a0, a1, a2, a3, qs + a_off + ksix * 32);
#pragma unroll
            for (int nbi = 0; nbi < 2; nbi++) {
                unsigned b0, b1;
                ldsm_x2(b0, b1, ks + (nb0 + nbi) * 8 * GROW + b_off + ksix * 32);
                mma_bf16(acc[nbi][0], acc[nbi][1], acc[nbi][2], acc[nbi][3],
                         a0, a1, a2, a3, b0, b1);
            }
        }
        __syncthreads();
    }

    float* Gp = g_G + ((b * NH_ + h) << 10);
    int row = lane >> 2, colp = 2 * (lane & 3);
#pragma unroll
    for (int nbi = 0; nbi < 2; nbi++) {
        int cbase = (nb0 + nbi) * 8 + colp;
        atomicAdd(&Gp[(mt * 16 + row) * 32 + cbase],         acc[nbi][0]);
        atomicAdd(&Gp[(mt * 16 + row) * 32 + cbase + 1],     acc[nbi][1]);
        atomicAdd(&Gp[(mt * 16 + row + 8) * 32 + cbase],     acc[nbi][2]);
        atomicAdd(&Gp[(mt * 16 + row + 8) * 32 + cbase + 1], acc[nbi][3]);
    }
}

// ---------------------------------------------------------------------------
// K3: softmax + compose M[b] = w_out @ blockdiag(attn heads). grid (6, B).
// ssq/ssk are the sum of the two conv half-plane partials.
// ---------------------------------------------------------------------------
__global__ __launch_bounds__(256) void compose_k(const float* __restrict__ temp,
                                                 const float* __restrict__ w_out) {
    extern __shared__ float cs[];
    float* A   = cs;          // [6*32*32]
    float* Wsh = cs + 6144;   // [32*192]
    __shared__ float sinvsh[C_];
    int oc = blockIdx.x, b = blockIdx.y;
    int o0 = oc * 32;
    int tid = threadIdx.x;

    if (tid < C_) {
        float sk = g_ssk[b * C_ + tid] + g_ssk[B_ * C_ + b * C_ + tid];
        sinvsh[tid] = 1.f / fmaxf(sqrtf(sk), 1e-12f);
    }
    for (int i = tid; i < 32 * 192; i += 256) {
        int o = i / 192, c = i - o * 192;
        Wsh[i] = w_out[(o0 + o) * C_ + c];
    }
    __syncthreads();
    if (tid < C_) {
        int h = tid >> 5, cl = tid & 31;
        float sq = g_ssq[b * C_ + tid] + g_ssq[B_ * C_ + b * C_ + tid];
        float nq = fmaxf(sqrtf(sq), 1e-12f);
        float sc = temp[h] / nq;
        const float* Gr = g_G + ((b * NH_ + h) << 10) + cl * HD_;
        const float* si = sinvsh + h * HD_;
        float row[32], mx = -3.4e38f;
#pragma unroll
        for (int d = 0; d < 32; d++) {
            float v = Gr[d] * sc * si[d];
            row[d] = v;
            mx = fmaxf(mx, v);
        }
        float s = 0.f;
#pragma unroll
        for (int d = 0; d < 32; d++) { row[d] = expf(row[d] - mx); s += row[d]; }
        float inv = 1.f / s;
#pragma unroll
        for (int d = 0; d < 32; d++) A[h * 1024 + cl * 32 + d] = row[d] * inv;
    }
    __syncthreads();
    float* Mb = g_M + (size_t)b * C_ * C_ + (size_t)o0 * C_;
    for (int i = tid; i < 32 * 192; i += 256) {
        int o = i / 192, g = i - o * 192;
        int h = g >> 5, d = g & 31;
        const float* wr = Wsh + o * 192 + h * 32;
        const float* Ar = A + h * 1024 + d;
        float acc = 0.f;
#pragma unroll
        for (int cl = 0; cl < 32; cl++) acc = fmaf(wr[cl], Ar[cl * 32], acc);
        Mb[i] = acc;
    }
}

// ---------------------------------------------------------------------------
// K4: out[b] = M[b](192x192) @ v[b](192xN) + b_out via mma.sync tf32
// (m16n8k8). 12 warps; A-fragments in regs; B [192k x 64n] tf32 smem
// (stride 72, conflict-free), double-buffered; 16 stages of n=64.
// ---------------------------------------------------------------------------
#define BSTR 72
#define BBUF (192 * BSTR)
#define GEMM_SMEM (2 * BBUF * 4)

__device__ __forceinline__ void mma_tf32(float& c0, float& c1, float& c2, float& c3,
                                         unsigned a0, unsigned a1, unsigned a2, unsigned a3,
                                         unsigned b0, unsigned b1) {
    asm volatile(
        "mma.sync.aligned.m16n8k8.row.col.f32.tf32.tf32.f32 "
        "{%0,%1,%2,%3}, {%4,%5,%6,%7}, {%8,%9}, {%0,%1,%2,%3};"
        : "+f"(c0), "+f"(c1), "+f"(c2), "+f"(c3)
        : "r"(a0), "r"(a1), "r"(a2), "r"(a3), "r"(b0), "r"(b1));
}

__global__ __launch_bounds__(384, 1) void gemm_out_k(const float* __restrict__ b_out,
                                                     float* __restrict__ out) {
    extern __shared__ unsigned Bs[];   // [2][192][BSTR] tf32
    int tid = threadIdx.x, wid = tid >> 5, lid = tid & 31;
    int b = blockIdx.y;
    int n0 = blockIdx.x * 1024;

    const float* Mg = g_M + (size_t)b * C_ * C_;
    const float* vb = g_v + (size_t)b * C_ * N_ + n0;

    int g = lid >> 2, t = lid & 3;
    int r0 = 16 * wid + g, r1 = r0 + 8;
    unsigned af[24][4];
#pragma unroll
    for (int j = 0; j < 24; j++) {
        af[j][0] = tf32r(Mg[(size_t)r0 * C_ + 8 * j + t]);
        af[j][1] = tf32r(Mg[(size_t)r1 * C_ + 8 * j + t]);
        af[j][2] = tf32r(Mg[(size_t)r0 * C_ + 8 * j + 4 + t]);
        af[j][3] = tf32r(Mg[(size_t)r1 * C_ + 8 * j + 4 + t]);
    }
    float bias_lo = b_out[r0], bias_hi = b_out[r1];

    {
        int row = tid >> 4, c4 = (tid & 15) << 2;
#pragma unroll
        for (int i = 0; i < 8; i++) {
            int kk = row + i * 24;
            float4 v = *(const float4*)(vb + (size_t)kk * N_ + c4);
            unsigned* dp = Bs + kk * BSTR + c4;
            dp[0] = tf32r(v.x); dp[1] = tf32r(v.y);
            dp[2] = tf32r(v.z); dp[3] = tf32r(v.w);
        }
    }
    __syncthreads();

    for (int s = 0; s < 16; s++) {
        float4 pf[8];
        if (s < 15) {
            int row = tid >> 4, c4 = (tid & 15) << 2;
#pragma unroll
            for (int i = 0; i < 8; i++) {
                int kk = row + i * 24;
                pf[i] = *(const float4*)(vb + (size_t)kk * N_ + (s + 1) * 64 + c4);
            }
        }
        const unsigned* Bc = Bs + (s & 1) * BBUF;
#pragma unroll
        for (int nb = 0; nb < 8; nb++) {
            float c0 = bias_lo, c1 = bias_lo, c2 = bias_hi, c3 = bias_hi;
            const unsigned* bp = Bc + 8 * nb + (lid >> 2) + (lid & 3) * BSTR;
#pragma unroll
            for (int j = 0; j < 24; j++) {
                unsigned b0 = bp[8 * j * BSTR];
                unsigned b1 = bp[(8 * j + 4) * BSTR];
                mma_tf32(c0, c1, c2, c3, af[j][0], af[j][1], af[j][2], af[j][3], b0, b1);
            }
            int col = n0 + s * 64 + 8 * nb + 2 * (lid & 3);
            *(float2*)(out + (size_t)(b * C_ + r0) * N_ + col) = make_float2(c0, c1);
            *(float2*)(out + (size_t)(b * C_ + r1) * N_ + col) = make_float2(c2, c3);
        }
        __syncthreads();
        if (s < 15) {
            int row = tid >> 4, c4 = (tid & 15) << 2;
            unsigned* Bn = Bs + ((s + 1) & 1) * BBUF;
#pragma unroll
            for (int i = 0; i < 8; i++) {
                int kk = row + i * 24;
                unsigned* dp = Bn + kk * BSTR + c4;
                dp[0] = tf32r(pf[i].x); dp[1] = tf32r(pf[i].y);
                dp[2] = tf32r(pf[i].z); dp[3] = tf32r(pf[i].w);
            }
            __syncthreads();
        }
    }
}

// ---------------------------------------------------------------------------
extern "C" void kernel_launch(void* const* d_in, const int* in_sizes, int n_in,
                              void* d_out, int out_size) {
    const float* x     = (const float*)d_in[0];
    const float* w_qkv = (const float*)d_in[1];
    const float* b_qkv = (const float*)d_in[2];
    const float* temp  = (const float*)d_in[3];
    const float* w_out = (const float*)d_in[4];
    const float* b_out = (const float*)d_in[5];
    float* out = (float*)d_out;

    (void)in_sizes; (void)n_in; (void)out_size;

    static int inited = 0;
    const int conv_smem = 66 * 132 * 4;
    const int comp_smem = (6144 + 32 * 192) * 4;
    if (!inited) {
        cudaFuncSetAttribute(conv_k,     cudaFuncAttributeMaxDynamicSharedMemorySize, conv_smem);
        cudaFuncSetAttribute(gram_k,     cudaFuncAttributeMaxDynamicSharedMemorySize, GRAM_SMEM);
        cudaFuncSetAttribute(compose_k,  cudaFuncAttributeMaxDynamicSharedMemorySize, comp_smem);
        cudaFuncSetAttribute(gemm_out_k, cudaFuncAttributeMaxDynamicSharedMemorySize, GEMM_SMEM);
        inited = 1;
    }

    // 7 launches; profiled launch (idx 3) = conv_k (verify issue-count fix).
    nop_k<<<1, 32>>>();
    nop_k<<<1, 32>>>();
    nop_k<<<1, 32>>>();
    conv_k<<<dim3(C_, 2, B_), 256, conv_smem>>>(x, w_qkv, b_qkv);
    gram_k<<<dim3(16, NH_, B_), 128, GRAM_SMEM>>>();
    compose_k<<<dim3(6, B_), 256, comp_smem>>>(temp, w_out);
    gemm_out_k<<<dim3(N_ / 1024, B_), 384, GEMM_SMEM>>>(b_out, out);
}

// round 13
// speedup vs baseline: 2.6876x; 1.0560x over previous
#include <cuda_runtime.h>
#include <cuda_bf16.h>

#define B_ 8
#define C_ 192
#define N_ 16384
#define NH_ 6
#define HD_ 32

// Scratch (device globals: allocation-free per harness rules)
__device__ __nv_bfloat16 g_q[B_*C_*N_];
__device__ __nv_bfloat16 g_k[B_*C_*N_];
__device__ float g_v[B_*C_*N_];
__device__ float g_ssq[2*B_*C_];   // two half-plane partials
__device__ float g_ssk[2*B_*C_];
__device__ float g_G[B_*NH_*HD_*HD_];
__device__ float g_M[B_*C_*C_];

__device__ __forceinline__ unsigned tf32r(float x) {
    unsigned u;
    asm("cvt.rna.tf32.f32 %0, %1;" : "=r"(u) : "f"(x));
    return u;
}
__device__ __forceinline__ unsigned su32(const void* p) {
    unsigned r;
    asm("{ .reg .u64 t; cvta.to.shared.u64 t, %1; cvt.u32.u64 %0, t; }"
        : "=r"(r) : "l"(p));
    return r;
}
// pack (lo=a, hi=b) into one bf16x2 word
__device__ __forceinline__ unsigned bf2(float lo, float hi) {
    unsigned r;
    asm("cvt.rn.bf16x2.f32 %0, %1, %2;" : "=r"(r) : "f"(hi), "f"(lo));
    return r;
}
#define CP_ASYNC16(s, g) asm volatile("cp.async.ca.shared.global [%0], [%1], 16;" :: "r"(s), "l"(g))
#define CP_COMMIT()      asm volatile("cp.async.commit_group;")
#define CP_WAIT(n)       asm volatile("cp.async.wait_group %0;" :: "n"(n))

__device__ __forceinline__ void ldsm_x4(unsigned& r0, unsigned& r1, unsigned& r2,
                                        unsigned& r3, unsigned addr) {
    asm volatile("ldmatrix.sync.aligned.m8n8.x4.shared.b16 {%0,%1,%2,%3}, [%4];"
                 : "=r"(r0), "=r"(r1), "=r"(r2), "=r"(r3) : "r"(addr));
}
__device__ __forceinline__ void ldsm_x2(unsigned& r0, unsigned& r1, unsigned addr) {
    asm volatile("ldmatrix.sync.aligned.m8n8.x2.shared.b16 {%0,%1}, [%2];"
                 : "=r"(r0), "=r"(r1) : "r"(addr));
}
__device__ __forceinline__ void mma_bf16(float& c0, float& c1, float& c2, float& c3,
                                         unsigned a0, unsigned a1, unsigned a2, unsigned a3,
                                         unsigned b0, unsigned b1) {
    asm volatile(
        "mma.sync.aligned.m16n8k16.row.col.f32.bf16.bf16.f32 "
        "{%0,%1,%2,%3}, {%4,%5,%6,%7}, {%8,%9}, {%0,%1,%2,%3};"
        : "+f"(c0), "+f"(c1), "+f"(c2), "+f"(c3)
        : "r"(a0), "r"(a1), "r"(a2), "r"(a3), "r"(b0), "r"(b1));
}

// ---------------------------------------------------------------------------
// K1: depthwise 3x3 conv, half-plane blocks (instruction-lean; round 12).
// ---------------------------------------------------------------------------
__global__ __launch_bounds__(256) void conv_k(const float* __restrict__ x,
                                              const float* __restrict__ w,
                                              const float* __restrict__ bias) {
    const int RS = 132;
    extern __shared__ float tile[];    // [66][132]
    int cin = blockIdx.x, half = blockIdx.y, b = blockIdx.z;
    int tid = threadIdx.x, wid = tid >> 5, lane = tid & 31;
    if (b == 0 && half == 0 && cin < 48) {
        float* Gz = g_G + cin * 1024;
        for (int i = tid; i < 1024; i += 256) Gz[i] = 0.f;
    }
    int r0 = half * 64;
    const float* xp = x + ((size_t)b * C_ + cin) * N_;
    for (int rr = wid; rr < 66; rr += 8) {
        int yy = r0 + rr - 1;
        bool rowok = (unsigned)yy < 128u;
        const float* rp = xp + yy * 128 - 1;
        float* tp = tile + rr * RS;
#pragma unroll
        for (int c = lane; c < 130; c += 32) {
            float v = 0.f;
            if (rowok && c >= 1 && c <= 128) v = rp[c];
            tp[c] = v;
        }
    }
    __syncthreads();

    int o0 = cin * 3;
    float w9[3][9], bs[3];
#pragma unroll
    for (int j = 0; j < 3; j++) {
        int o = o0 + j;
        bs[j] = bias[o];
#pragma unroll
        for (int t = 0; t < 9; t++) w9[j][t] = w[o * 9 + t];
    }
    size_t hoff = (size_t)r0 * 128;

    if (cin < 128) {
        __nv_bfloat16* dst[3];
#pragma unroll
        for (int j = 0; j < 3; j++) {
            int o = o0 + j;
            if (o < C_) dst[j] = g_q + ((size_t)b * C_ + o) * N_ + hoff;
            else        dst[j] = g_k + ((size_t)b * C_ + (o - C_)) * N_ + hoff;
        }
        float ss[3] = {0.f, 0.f, 0.f};
#pragma unroll
        for (int q = 0; q < 8; q++) {
            int p4 = tid + q * 256;
            int r = p4 >> 5, cc = (p4 & 31) << 2;
            const float* trow = tile + r * RS + cc;
            float xr[3][6];
#pragma unroll
            for (int dy = 0; dy < 3; dy++) {
                float4 f = *(const float4*)(trow + dy * RS);
                float2 g2 = *(const float2*)(trow + dy * RS + 4);
                xr[dy][0] = f.x; xr[dy][1] = f.y; xr[dy][2] = f.z;
                xr[dy][3] = f.w; xr[dy][4] = g2.x; xr[dy][5] = g2.y;
            }
#pragma unroll
            for (int j = 0; j < 3; j++) {
                float a[4];
#pragma unroll
                for (int i = 0; i < 4; i++) {
                    float acc = bs[j];
#pragma unroll
                    for (int dy = 0; dy < 3; dy++)
#pragma unroll
                        for (int dx = 0; dx < 3; dx++)
                            acc = fmaf(xr[dy][i + dx], w9[j][dy * 3 + dx], acc);
                    a[i] = acc;
                }
                ss[j] = fmaf(a[0], a[0], fmaf(a[1], a[1],
                         fmaf(a[2], a[2], fmaf(a[3], a[3], ss[j]))));
                uint2 pk = make_uint2(bf2(a[0], a[1]), bf2(a[2], a[3]));
                *(uint2*)(dst[j] + p4 * 4) = pk;
            }
        }
        __shared__ float red[3][8];
#pragma unroll
        for (int j = 0; j < 3; j++) {
            float v = ss[j];
#pragma unroll
            for (int off = 16; off > 0; off >>= 1) v += __shfl_xor_sync(0xffffffffu, v, off);
            if (lane == 0) red[j][wid] = v;
        }
        __syncthreads();
        if (tid < 3) {
            float t = 0.f;
#pragma unroll
            for (int wd = 0; wd < 8; wd++) t += red[tid][wd];
            int o = o0 + tid;
            int part = half * B_ * C_;
            if (o < C_) g_ssq[part + b * C_ + o] = t;
            else        g_ssk[part + b * C_ + (o - C_)] = t;
        }
    } else {
        float* dst[3];
#pragma unroll
        for (int j = 0; j < 3; j++)
            dst[j] = g_v + ((size_t)b * C_ + (o0 + j - 2 * C_)) * N_ + hoff;
#pragma unroll
        for (int q = 0; q < 8; q++) {
            int p4 = tid + q * 256;
            int r = p4 >> 5, cc = (p4 & 31) << 2;
            const float* trow = tile + r * RS + cc;
            float xr[3][6];
#pragma unroll
            for (int dy = 0; dy < 3; dy++) {
                float4 f = *(const float4*)(trow + dy * RS);
                float2 g2 = *(const float2*)(trow + dy * RS + 4);
                xr[dy][0] = f.x; xr[dy][1] = f.y; xr[dy][2] = f.z;
                xr[dy][3] = f.w; xr[dy][4] = g2.x; xr[dy][5] = g2.y;
            }
#pragma unroll
            for (int j = 0; j < 3; j++) {
                float a[4];
#pragma unroll
                for (int i = 0; i < 4; i++) {
                    float acc = bs[j];
#pragma unroll
                    for (int dy = 0; dy < 3; dy++)
#pragma unroll
                        for (int dx = 0; dx < 3; dx++)
                            acc = fmaf(xr[dy][i + dx], w9[j][dy * 3 + dx], acc);
                    a[i] = acc;
                }
                *(float4*)(dst[j] + p4 * 4) = make_float4(a[0], a[1], a[2], a[3]);
            }
        }
    }
}

// ---------------------------------------------------------------------------
// K2: gram G[b,h] += q_h @ k_h^T via mma.sync bf16 (m16n8k16) + ldmatrix.
// ---------------------------------------------------------------------------
#define GROW 272
#define GARR (32 * GROW)
#define GBUF (2 * GARR)
#define GRAM_SMEM (2 * GBUF)

__global__ __launch_bounds__(128) void gram_k() {
    extern __shared__ char gsm[];
    unsigned smem_base = su32(gsm);
    int chunk = blockIdx.x, h = blockIdx.y, b = blockIdx.z;
    const __nv_bfloat16* qb = g_q + ((size_t)b * C_ + h * HD_) * N_;
    const __nv_bfloat16* kb = g_k + ((size_t)b * C_ + h * HD_) * N_;
    int tid = threadIdx.x, wid = tid >> 5, lane = tid & 31;
    int n0 = chunk * 1024;

    int mt = wid & 1;
    int nb0 = (wid >> 1) * 2;

    auto stage = [&](int sub, int buf) {
        unsigned dstq = smem_base + buf * GBUF;
        unsigned dstk = dstq + GARR;
        int r = tid >> 4, s16 = tid & 15;
#pragma unroll
        for (int i = 0; i < 4; i++) {
            int row = r + i * 8;
            const __nv_bfloat16* sq = qb + (size_t)row * N_ + n0 + sub * 128 + s16 * 8;
            const __nv_bfloat16* sk = kb + (size_t)row * N_ + n0 + sub * 128 + s16 * 8;
            CP_ASYNC16(dstq + row * GROW + s16 * 16, sq);
            CP_ASYNC16(dstk + row * GROW + s16 * 16, sk);
        }
        CP_COMMIT();
    };

    stage(0, 0);

    float acc[2][4];
#pragma unroll
    for (int nbi = 0; nbi < 2; nbi++)
#pragma unroll
        for (int p = 0; p < 4; p++) acc[nbi][p] = 0.f;

    unsigned a_off = (lane & 15) * GROW + (lane >> 4) * 16;
    unsigned b_off = (lane & 7) * GROW + ((lane >> 3) & 1) * 16;

    for (int sub = 0; sub < 8; sub++) {
        int buf = sub & 1;
        if (sub < 7) { stage(sub + 1, buf ^ 1); CP_WAIT(1); }
        else         { CP_WAIT(0); }
        __syncthreads();
        unsigned qs = smem_base + buf * GBUF + mt * 16 * GROW;
        unsigned ks = smem_base + buf * GBUF + GARR;
#pragma unroll
        for (int ksix = 0; ksix < 8; ksix++) {
            unsigned a0, a1, a2, a3;
            ldsm_x4(a0, a1, a2, a3, qs + a_off + ksix * 32);
#pragma unroll
            for (int nbi = 0; nbi < 2; nbi++) {
                unsigned b0, b1;
                ldsm_x2(b0, b1, ks + (nb0 + nbi) * 8 * GROW + b_off + ksix * 32);
                mma_bf16(acc[nbi][0], acc[nbi][1], acc[nbi][2], acc[nbi][3],
                         a0, a1, a2, a3, b0, b1);
            }
        }
        __syncthreads();
    }

    float* Gp = g_G + ((b * NH_ + h) << 10);
    int row = lane >> 2, colp = 2 * (lane & 3);
#pragma unroll
    for (int nbi = 0; nbi < 2; nbi++) {
        int cbase = (nb0 + nbi) * 8 + colp;
        atomicAdd(&Gp[(mt * 16 + row) * 32 + cbase],         acc[nbi][0]);
        atomicAdd(&Gp[(mt * 16 + row) * 32 + cbase + 1],     acc[nbi][1]);
        atomicAdd(&Gp[(mt * 16 + row + 8) * 32 + cbase],     acc[nbi][2]);
        atomicAdd(&Gp[(mt * 16 + row + 8) * 32 + cbase + 1], acc[nbi][3]);
    }
}

// ---------------------------------------------------------------------------
// K3: softmax + compose M[b] = w_out @ blockdiag(attn heads). grid (6, B).
// ---------------------------------------------------------------------------
__global__ __launch_bounds__(256) void compose_k(const float* __restrict__ temp,
                                                 const float* __restrict__ w_out) {
    extern __shared__ float cs[];
    float* A   = cs;          // [6*32*32]
    float* Wsh = cs + 6144;   // [32*192]
    __shared__ float sinvsh[C_];
    int oc = blockIdx.x, b = blockIdx.y;
    int o0 = oc * 32;
    int tid = threadIdx.x;

    if (tid < C_) {
        float sk = g_ssk[b * C_ + tid] + g_ssk[B_ * C_ + b * C_ + tid];
        sinvsh[tid] = 1.f / fmaxf(sqrtf(sk), 1e-12f);
    }
    for (int i = tid; i < 32 * 192; i += 256) {
        int o = i / 192, c = i - o * 192;
        Wsh[i] = w_out[(o0 + o) * C_ + c];
    }
    __syncthreads();
    if (tid < C_) {
        int h = tid >> 5, cl = tid & 31;
        float sq = g_ssq[b * C_ + tid] + g_ssq[B_ * C_ + b * C_ + tid];
        float nq = fmaxf(sqrtf(sq), 1e-12f);
        float sc = temp[h] / nq;
        const float* Gr = g_G + ((b * NH_ + h) << 10) + cl * HD_;
        const float* si = sinvsh + h * HD_;
        float row[32], mx = -3.4e38f;
#pragma unroll
        for (int d = 0; d < 32; d++) {
            float v = Gr[d] * sc * si[d];
            row[d] = v;
            mx = fmaxf(mx, v);
        }
        float s = 0.f;
#pragma unroll
        for (int d = 0; d < 32; d++) { row[d] = expf(row[d] - mx); s += row[d]; }
        float inv = 1.f / s;
#pragma unroll
        for (int d = 0; d < 32; d++) A[h * 1024 + cl * 32 + d] = row[d] * inv;
    }
    __syncthreads();
    float* Mb = g_M + (size_t)b * C_ * C_ + (size_t)o0 * C_;
    for (int i = tid; i < 32 * 192; i += 256) {
        int o = i / 192, g = i - o * 192;
        int h = g >> 5, d = g & 31;
        const float* wr = Wsh + o * 192 + h * 32;
        const float* Ar = A + h * 1024 + d;
        float acc = 0.f;
#pragma unroll
        for (int cl = 0; cl < 32; cl++) acc = fmaf(wr[cl], Ar[cl * 32], acc);
        Mb[i] = acc;
    }
}

// ---------------------------------------------------------------------------
// K4: out[b] = M[b](192x192) @ v[b](192xN) + b_out via mma.sync tf32
// (m16n8k8). 12 warps; A-fragments (rna-converted) in regs.
// B: raw fp32 staged straight into smem via cp.async (HMMA truncates fp32
// bits to tf32 on read -> no cvt/STS staging chain). Stride 72, conflict-
// free fragment reads; double-buffered, 16 stages of n=64.
// ---------------------------------------------------------------------------
#define BSTR 72
#define BBUF (192 * BSTR)
#define GEMM_SMEM (2 * BBUF * 4)

__device__ __forceinline__ void mma_tf32(float& c0, float& c1, float& c2, float& c3,
                                         unsigned a0, unsigned a1, unsigned a2, unsigned a3,
                                         unsigned b0, unsigned b1) {
    asm volatile(
        "mma.sync.aligned.m16n8k8.row.col.f32.tf32.tf32.f32 "
        "{%0,%1,%2,%3}, {%4,%5,%6,%7}, {%8,%9}, {%0,%1,%2,%3};"
        : "+f"(c0), "+f"(c1), "+f"(c2), "+f"(c3)
        : "r"(a0), "r"(a1), "r"(a2), "r"(a3), "r"(b0), "r"(b1));
}

__global__ __launch_bounds__(384, 1) void gemm_out_k(const float* __restrict__ b_out,
                                                     float* __restrict__ out) {
    extern __shared__ unsigned Bs[];   // [2][192][BSTR] raw fp32 bits
    int tid = threadIdx.x, wid = tid >> 5, lid = tid & 31;
    int b = blockIdx.y;
    int n0 = blockIdx.x * 1024;

    const float* Mg = g_M + (size_t)b * C_ * C_;
    const float* vb = g_v + (size_t)b * C_ * N_ + n0;
    unsigned sbase = su32(Bs);

    // A fragments in registers (rna-rounded tf32)
    int g = lid >> 2, t = lid & 3;
    int r0 = 16 * wid + g, r1 = r0 + 8;
    unsigned af[24][4];
#pragma unroll
    for (int j = 0; j < 24; j++) {
        af[j][0] = tf32r(Mg[(size_t)r0 * C_ + 8 * j + t]);
        af[j][1] = tf32r(Mg[(size_t)r1 * C_ + 8 * j + t]);
        af[j][2] = tf32r(Mg[(size_t)r0 * C_ + 8 * j + 4 + t]);
        af[j][3] = tf32r(Mg[(size_t)r1 * C_ + 8 * j + 4 + t]);
    }
    float bias_lo = b_out[r0], bias_hi = b_out[r1];

    int srow = tid >> 4, sc4 = (tid & 15) << 2;
    auto stageB = [&](int s, int buf) {
        unsigned dbase = sbase + (unsigned)buf * (BBUF * 4);
#pragma unroll
        for (int i = 0; i < 8; i++) {
            int kk = srow + i * 24;
            CP_ASYNC16(dbase + (kk * BSTR + sc4) * 4,
                       vb + (size_t)kk * N_ + s * 64 + sc4);
        }
        CP_COMMIT();
    };

    stageB(0, 0);

    for (int s = 0; s < 16; s++) {
        int buf = s & 1;
        if (s < 15) { stageB(s + 1, buf ^ 1); CP_WAIT(1); }
        else        { CP_WAIT(0); }
        __syncthreads();
        const unsigned* Bc = Bs + buf * BBUF;
#pragma unroll
        for (int nb = 0; nb < 8; nb++) {
            float c0 = bias_lo, c1 = bias_lo, c2 = bias_hi, c3 = bias_hi;
            const unsigned* bp = Bc + 8 * nb + (lid >> 2) + (lid & 3) * BSTR;
#pragma unroll
            for (int j = 0; j < 24; j++) {
                unsigned b0 = bp[8 * j * BSTR];
                unsigned b1 = bp[(8 * j + 4) * BSTR];
                mma_tf32(c0, c1, c2, c3, af[j][0], af[j][1], af[j][2], af[j][3], b0, b1);
            }
            int col = n0 + s * 64 + 8 * nb + 2 * (lid & 3);
            *(float2*)(out + (size_t)(b * C_ + r0) * N_ + col) = make_float2(c0, c1);
            *(float2*)(out + (size_t)(b * C_ + r1) * N_ + col) = make_float2(c2, c3);
        }
        __syncthreads();
    }
}

// ---------------------------------------------------------------------------
extern "C" void kernel_launch(void* const* d_in, const int* in_sizes, int n_in,
                              void* d_out, int out_size) {
    const float* x     = (const float*)d_in[0];
    const float* w_qkv = (const float*)d_in[1];
    const float* b_qkv = (const float*)d_in[2];
    const float* temp  = (const float*)d_in[3];
    const float* w_out = (const float*)d_in[4];
    const float* b_out = (const float*)d_in[5];
    float* out = (float*)d_out;

    (void)in_sizes; (void)n_in; (void)out_size;

    static int inited = 0;
    const int conv_smem = 66 * 132 * 4;
    const int comp_smem = (6144 + 32 * 192) * 4;
    if (!inited) {
        cudaFuncSetAttribute(conv_k,     cudaFuncAttributeMaxDynamicSharedMemorySize, conv_smem);
        cudaFuncSetAttribute(gram_k,     cudaFuncAttributeMaxDynamicSharedMemorySize, GRAM_SMEM);
        cudaFuncSetAttribute(compose_k,  cudaFuncAttributeMaxDynamicSharedMemorySize, comp_smem);
        cudaFuncSetAttribute(gemm_out_k, cudaFuncAttributeMaxDynamicSharedMemorySize, GEMM_SMEM);
        inited = 1;
    }

    // 4 launches; profiled launch (idx 3) = gemm_out_k (verify cp.async staging).
    conv_k<<<dim3(C_, 2, B_), 256, conv_smem>>>(x, w_qkv, b_qkv);
    gram_k<<<dim3(16, NH_, B_), 128, GRAM_SMEM>>>();
    compose_k<<<dim3(6, B_), 256, comp_smem>>>(temp, w_out);
    gemm_out_k<<<dim3(N_ / 1024, B_), 384, GEMM_SMEM>>>(b_out, out);
}

// round 14
// speedup vs baseline: 2.9673x; 1.1041x over previous
#include <cuda_runtime.h>
#include <cuda_bf16.h>
#include <cuda_fp16.h>

#define B_ 8
#define C_ 192
#define N_ 16384
#define NH_ 6
#define HD_ 32

// Scratch (device globals: allocation-free per harness rules)
__device__ __nv_bfloat16 g_q[B_*C_*N_];
__device__ __nv_bfloat16 g_k[B_*C_*N_];
__device__ __half g_v[B_*C_*N_];
__device__ float g_ssq[2*B_*C_];   // two half-plane partials
__device__ float g_ssk[2*B_*C_];
__device__ float g_G[B_*NH_*HD_*HD_];
__device__ float g_M[B_*C_*C_];

__device__ __forceinline__ unsigned su32(const void* p) {
    unsigned r;
    asm("{ .reg .u64 t; cvta.to.shared.u64 t, %1; cvt.u32.u64 %0, t; }"
        : "=r"(r) : "l"(p));
    return r;
}
// pack (lo=a, hi=b) into one bf16x2 word
__device__ __forceinline__ unsigned bf2(float lo, float hi) {
    unsigned r;
    asm("cvt.rn.bf16x2.f32 %0, %1, %2;" : "=r"(r) : "f"(hi), "f"(lo));
    return r;
}
#define CP_ASYNC16(s, g) asm volatile("cp.async.ca.shared.global [%0], [%1], 16;" :: "r"(s), "l"(g))
#define CP_COMMIT()      asm volatile("cp.async.commit_group;")
#define CP_WAIT(n)       asm volatile("cp.async.wait_group %0;" :: "n"(n))

__device__ __forceinline__ void ldsm_x4(unsigned& r0, unsigned& r1, unsigned& r2,
                                        unsigned& r3, unsigned addr) {
    asm volatile("ldmatrix.sync.aligned.m8n8.x4.shared.b16 {%0,%1,%2,%3}, [%4];"
                 : "=r"(r0), "=r"(r1), "=r"(r2), "=r"(r3) : "r"(addr));
}
__device__ __forceinline__ void ldsm_x2(unsigned& r0, unsigned& r1, unsigned addr) {
    asm volatile("ldmatrix.sync.aligned.m8n8.x2.shared.b16 {%0,%1}, [%2];"
                 : "=r"(r0), "=r"(r1) : "r"(addr));
}
__device__ __forceinline__ void ldsm_x4_t(unsigned& r0, unsigned& r1, unsigned& r2,
                                          unsigned& r3, unsigned addr) {
    asm volatile("ldmatrix.sync.aligned.m8n8.x4.trans.shared.b16 {%0,%1,%2,%3}, [%4];"
                 : "=r"(r0), "=r"(r1), "=r"(r2), "=r"(r3) : "r"(addr));
}
__device__ __forceinline__ void mma_bf16(float& c0, float& c1, float& c2, float& c3,
                                         unsigned a0, unsigned a1, unsigned a2, unsigned a3,
                                         unsigned b0, unsigned b1) {
    asm volatile(
        "mma.sync.aligned.m16n8k16.row.col.f32.bf16.bf16.f32 "
        "{%0,%1,%2,%3}, {%4,%5,%6,%7}, {%8,%9}, {%0,%1,%2,%3};"
        : "+f"(c0), "+f"(c1), "+f"(c2), "+f"(c3)
        : "r"(a0), "r"(a1), "r"(a2), "r"(a3), "r"(b0), "r"(b1));
}
__device__ __forceinline__ void mma_fp16(float& c0, float& c1, float& c2, float& c3,
                                         unsigned a0, unsigned a1, unsigned a2, unsigned a3,
                                         unsigned b0, unsigned b1) {
    asm volatile(
        "mma.sync.aligned.m16n8k16.row.col.f32.f16.f16.f32 "
        "{%0,%1,%2,%3}, {%4,%5,%6,%7}, {%8,%9}, {%0,%1,%2,%3};"
        : "+f"(c0), "+f"(c1), "+f"(c2), "+f"(c3)
        : "r"(a0), "r"(a1), "r"(a2), "r"(a3), "r"(b0), "r"(b1));
}

// ---------------------------------------------------------------------------
// K1: depthwise 3x3 conv, half-plane blocks (instruction-lean).
// q/k -> bf16 (+ssq/ssk partials); v -> fp16.
// ---------------------------------------------------------------------------
__global__ __launch_bounds__(256) void conv_k(const float* __restrict__ x,
                                              const float* __restrict__ w,
                                              const float* __restrict__ bias) {
    const int RS = 132;
    extern __shared__ float tile[];    // [66][132]
    int cin = blockIdx.x, half = blockIdx.y, b = blockIdx.z;
    int tid = threadIdx.x, wid = tid >> 5, lane = tid & 31;
    if (b == 0 && half == 0 && cin < 48) {
        float* Gz = g_G + cin * 1024;
        for (int i = tid; i < 1024; i += 256) Gz[i] = 0.f;
    }
    int r0 = half * 64;
    const float* xp = x + ((size_t)b * C_ + cin) * N_;
    for (int rr = wid; rr < 66; rr += 8) {
        int yy = r0 + rr - 1;
        bool rowok = (unsigned)yy < 128u;
        const float* rp = xp + yy * 128 - 1;
        float* tp = tile + rr * RS;
#pragma unroll
        for (int c = lane; c < 130; c += 32) {
            float v = 0.f;
            if (rowok && c >= 1 && c <= 128) v = rp[c];
            tp[c] = v;
        }
    }
    __syncthreads();

    int o0 = cin * 3;
    float w9[3][9], bs[3];
#pragma unroll
    for (int j = 0; j < 3; j++) {
        int o = o0 + j;
        bs[j] = bias[o];
#pragma unroll
        for (int t = 0; t < 9; t++) w9[j][t] = w[o * 9 + t];
    }
    size_t hoff = (size_t)r0 * 128;

    if (cin < 128) {
        __nv_bfloat16* dst[3];
#pragma unroll
        for (int j = 0; j < 3; j++) {
            int o = o0 + j;
            if (o < C_) dst[j] = g_q + ((size_t)b * C_ + o) * N_ + hoff;
            else        dst[j] = g_k + ((size_t)b * C_ + (o - C_)) * N_ + hoff;
        }
        float ss[3] = {0.f, 0.f, 0.f};
#pragma unroll
        for (int q = 0; q < 8; q++) {
            int p4 = tid + q * 256;
            int r = p4 >> 5, cc = (p4 & 31) << 2;
            const float* trow = tile + r * RS + cc;
            float xr[3][6];
#pragma unroll
            for (int dy = 0; dy < 3; dy++) {
                float4 f = *(const float4*)(trow + dy * RS);
                float2 g2 = *(const float2*)(trow + dy * RS + 4);
                xr[dy][0] = f.x; xr[dy][1] = f.y; xr[dy][2] = f.z;
                xr[dy][3] = f.w; xr[dy][4] = g2.x; xr[dy][5] = g2.y;
            }
#pragma unroll
            for (int j = 0; j < 3; j++) {
                float a[4];
#pragma unroll
                for (int i = 0; i < 4; i++) {
                    float acc = bs[j];
#pragma unroll
                    for (int dy = 0; dy < 3; dy++)
#pragma unroll
                        for (int dx = 0; dx < 3; dx++)
                            acc = fmaf(xr[dy][i + dx], w9[j][dy * 3 + dx], acc);
                    a[i] = acc;
                }
                ss[j] = fmaf(a[0], a[0], fmaf(a[1], a[1],
                         fmaf(a[2], a[2], fmaf(a[3], a[3], ss[j]))));
                uint2 pk = make_uint2(bf2(a[0], a[1]), bf2(a[2], a[3]));
                *(uint2*)(dst[j] + p4 * 4) = pk;
            }
        }
        __shared__ float red[3][8];
#pragma unroll
        for (int j = 0; j < 3; j++) {
            float v = ss[j];
#pragma unroll
            for (int off = 16; off > 0; off >>= 1) v += __shfl_xor_sync(0xffffffffu, v, off);
            if (lane == 0) red[j][wid] = v;
        }
        __syncthreads();
        if (tid < 3) {
            float t = 0.f;
#pragma unroll
            for (int wd = 0; wd < 8; wd++) t += red[tid][wd];
            int o = o0 + tid;
            int part = half * B_ * C_;
            if (o < C_) g_ssq[part + b * C_ + o] = t;
            else        g_ssk[part + b * C_ + (o - C_)] = t;
        }
    } else {
        __half* dst[3];
#pragma unroll
        for (int j = 0; j < 3; j++)
            dst[j] = g_v + ((size_t)b * C_ + (o0 + j - 2 * C_)) * N_ + hoff;
#pragma unroll
        for (int q = 0; q < 8; q++) {
            int p4 = tid + q * 256;
            int r = p4 >> 5, cc = (p4 & 31) << 2;
            const float* trow = tile + r * RS + cc;
            float xr[3][6];
#pragma unroll
            for (int dy = 0; dy < 3; dy++) {
                float4 f = *(const float4*)(trow + dy * RS);
                float2 g2 = *(const float2*)(trow + dy * RS + 4);
                xr[dy][0] = f.x; xr[dy][1] = f.y; xr[dy][2] = f.z;
                xr[dy][3] = f.w; xr[dy][4] = g2.x; xr[dy][5] = g2.y;
            }
#pragma unroll
            for (int j = 0; j < 3; j++) {
                float a[4];
#pragma unroll
                for (int i = 0; i < 4; i++) {
                    float acc = bs[j];
#pragma unroll
                    for (int dy = 0; dy < 3; dy++)
#pragma unroll
                        for (int dx = 0; dx < 3; dx++)
                            acc = fmaf(xr[dy][i + dx], w9[j][dy * 3 + dx], acc);
                    a[i] = acc;
                }
                __half2 h01 = __floats2half2_rn(a[0], a[1]);
                __half2 h23 = __floats2half2_rn(a[2], a[3]);
                uint2 pk = make_uint2(*(unsigned*)&h01, *(unsigned*)&h23);
                *(uint2*)(dst[j] + p4 * 4) = pk;
            }
        }
    }
}

// ---------------------------------------------------------------------------
// K2: gram G[b,h] += q_h @ k_h^T via mma.sync bf16 (m16n8k16) + ldmatrix.
// ---------------------------------------------------------------------------
#define GROW 272
#define GARR (32 * GROW)
#define GBUF (2 * GARR)
#define GRAM_SMEM (2 * GBUF)

__global__ __launch_bounds__(128) void gram_k() {
    extern __shared__ char gsm[];
    unsigned smem_base = su32(gsm);
    int chunk = blockIdx.x, h = blockIdx.y, b = blockIdx.z;
    const __nv_bfloat16* qb = g_q + ((size_t)b * C_ + h * HD_) * N_;
    const __nv_bfloat16* kb = g_k + ((size_t)b * C_ + h * HD_) * N_;
    int tid = threadIdx.x, wid = tid >> 5, lane = tid & 31;
    int n0 = chunk * 1024;

    int mt = wid & 1;
    int nb0 = (wid >> 1) * 2;

    auto stage = [&](int sub, int buf) {
        unsigned dstq = smem_base + buf * GBUF;
        unsigned dstk = dstq + GARR;
        int r = tid >> 4, s16 = tid & 15;
#pragma unroll
        for (int i = 0; i < 4; i++) {
            int row = r + i * 8;
            const __nv_bfloat16* sq = qb + (size_t)row * N_ + n0 + sub * 128 + s16 * 8;
            const __nv_bfloat16* sk = kb + (size_t)row * N_ + n0 + sub * 128 + s16 * 8;
            CP_ASYNC16(dstq + row * GROW + s16 * 16, sq);
            CP_ASYNC16(dstk + row * GROW + s16 * 16, sk);
        }
        CP_COMMIT();
    };

    stage(0, 0);

    float acc[2][4];
#pragma unroll
    for (int nbi = 0; nbi < 2; nbi++)
#pragma unroll
        for (int p = 0; p < 4; p++) acc[nbi][p] = 0.f;

    unsigned a_off = (lane & 15) * GROW + (lane >> 4) * 16;
    unsigned b_off = (lane & 7) * GROW + ((lane >> 3) & 1) * 16;

    for (int sub = 0; sub < 8; sub++) {
        int buf = sub & 1;
        if (sub < 7) { stage(sub + 1, buf ^ 1); CP_WAIT(1); }
        else         { CP_WAIT(0); }
        __syncthreads();
        unsigned qs = smem_base + buf * GBUF + mt * 16 * GROW;
        unsigned ks = smem_base + buf * GBUF + GARR;
#pragma unroll
        for (int ksix = 0; ksix < 8; ksix++) {
            unsigned a0, a1, a2, a3;
            ldsm_x4(a0, a1, a2, a3, qs + a_off + ksix * 32);
#pragma unroll
            for (int nbi = 0; nbi < 2; nbi++) {
                unsigned b0, b1;
                ldsm_x2(b0, b1, ks + (nb0 + nbi) * 8 * GROW + b_off + ksix * 32);
                mma_bf16(acc[nbi][0], acc[nbi][1], acc[nbi][2], acc[nbi][3],
                         a0, a1, a2, a3, b0, b1);
            }
        }
        __syncthreads();
    }

    float* Gp = g_G + ((b * NH_ + h) << 10);
    int row = lane >> 2, colp = 2 * (lane & 3);
#pragma unroll
    for (int nbi = 0; nbi < 2; nbi++) {
        int cbase = (nb0 + nbi) * 8 + colp;
        atomicAdd(&Gp[(mt * 16 + row) * 32 + cbase],         acc[nbi][0]);
        atomicAdd(&Gp[(mt * 16 + row) * 32 + cbase + 1],     acc[nbi][1]);
        atomicAdd(&Gp[(mt * 16 + row + 8) * 32 + cbase],     acc[nbi][2]);
        atomicAdd(&Gp[(mt * 16 + row + 8) * 32 + cbase + 1], acc[nbi][3]);
    }
}

// ---------------------------------------------------------------------------
// K3: softmax + compose M[b] = w_out @ blockdiag(attn heads). grid (6, B).
// ---------------------------------------------------------------------------
__global__ __launch_bounds__(256) void compose_k(const float* __restrict__ temp,
                                                 const float* __restrict__ w_out) {
    extern __shared__ float cs[];
    float* A   = cs;          // [6*32*32]
    float* Wsh = cs + 6144;   // [32*192]
    __shared__ float sinvsh[C_];
    int oc = blockIdx.x, b = blockIdx.y;
    int o0 = oc * 32;
    int tid = threadIdx.x;

    if (tid < C_) {
        float sk = g_ssk[b * C_ + tid] + g_ssk[B_ * C_ + b * C_ + tid];
        sinvsh[tid] = 1.f / fmaxf(sqrtf(sk), 1e-12f);
    }
    for (int i = tid; i < 32 * 192; i += 256) {
        int o = i / 192, c = i - o * 192;
        Wsh[i] = w_out[(o0 + o) * C_ + c];
    }
    __syncthreads();
    if (tid < C_) {
        int h = tid >> 5, cl = tid & 31;
        float sq = g_ssq[b * C_ + tid] + g_ssq[B_ * C_ + b * C_ + tid];
        float nq = fmaxf(sqrtf(sq), 1e-12f);
        float sc = temp[h] / nq;
        const float* Gr = g_G + ((b * NH_ + h) << 10) + cl * HD_;
        const float* si = sinvsh + h * HD_;
        float row[32], mx = -3.4e38f;
#pragma unroll
        for (int d = 0; d < 32; d++) {
            float v = Gr[d] * sc * si[d];
            row[d] = v;
            mx = fmaxf(mx, v);
        }
        float s = 0.f;
#pragma unroll
        for (int d = 0; d < 32; d++) { row[d] = expf(row[d] - mx); s += row[d]; }
        float inv = 1.f / s;
#pragma unroll
        for (int d = 0; d < 32; d++) A[h * 1024 + cl * 32 + d] = row[d] * inv;
    }
    __syncthreads();
    float* Mb = g_M + (size_t)b * C_ * C_ + (size_t)o0 * C_;
    for (int i = tid; i < 32 * 192; i += 256) {
        int o = i / 192, g = i - o * 192;
        int h = g >> 5, d = g & 31;
        const float* wr = Wsh + o * 192 + h * 32;
        const float* Ar = A + h * 1024 + d;
        float acc = 0.f;
#pragma unroll
        for (int cl = 0; cl < 32; cl++) acc = fmaf(wr[cl], Ar[cl * 32], acc);
        Mb[i] = acc;
    }
}

// ---------------------------------------------------------------------------
// K4: out[b] = M[b](192x192) @ v[b](192xN) + b_out via mma.sync fp16
// (m16n8k16, f32 accum). A = M split hi/lo fp16 (≈22 mantissa bits) in regs;
// B = v fp16 [192k x 64n-contig] smem tile, fragments via ldmatrix.x4.trans,
// cp.async-staged, double-buffered; 16 stages of n=64.
// ---------------------------------------------------------------------------
#define KSTRB 144                 // bytes per k-row (64 halves + 8 pad)
#define BTILEB (192 * KSTRB)      // bytes per buffer = 27648
#define GEMM_SMEM (2 * BTILEB)    // 55296

__global__ __launch_bounds__(384, 1) void gemm_out_k(const float* __restrict__ b_out,
                                                     float* __restrict__ out) {
    extern __shared__ char Bsm[];
    unsigned sbase = su32(Bsm);
    int tid = threadIdx.x, wid = tid >> 5, lid = tid & 31;
    int b = blockIdx.y;
    int n0 = blockIdx.x * 1024;

    const float* Mg = g_M + (size_t)b * C_ * C_;
    const __half* vb = g_v + (size_t)b * C_ * N_ + n0;

    // ---- A fragments: M rows split hi/lo fp16, packed half2, in regs ----
    int g = lid >> 2, t = lid & 3;
    int r0 = 16 * wid + g, r1 = r0 + 8;
    unsigned ah[12][4], al[12][4];
#pragma unroll
    for (int j = 0; j < 12; j++) {
        const float* m0 = Mg + (size_t)r0 * C_ + 16 * j + 2 * t;
        const float* m1 = Mg + (size_t)r1 * C_ + 16 * j + 2 * t;
        float v4[4][2] = {{m0[0], m0[1]}, {m1[0], m1[1]},
                          {m0[8], m0[9]}, {m1[8], m1[9]}};
#pragma unroll
        for (int p = 0; p < 4; p++) {
            __half h0 = __float2half_rn(v4[p][0]);
            __half h1 = __float2half_rn(v4[p][1]);
            __half l0 = __float2half_rn(v4[p][0] - __half2float(h0));
            __half l1 = __float2half_rn(v4[p][1] - __half2float(h1));
            __half2 hh = __halves2half2(h0, h1);
            __half2 ll = __halves2half2(l0, l1);
            ah[j][p] = *(unsigned*)&hh;
            al[j][p] = *(unsigned*)&ll;
        }
    }
    float bias_lo = b_out[r0], bias_hi = b_out[r1];

    auto stageB = [&](int s, int buf) {
        unsigned dbase = sbase + (unsigned)buf * BTILEB;
#pragma unroll
        for (int i = 0; i < 4; i++) {
            int e = tid + i * 384;
            int kk = e >> 3, c8 = (e & 7) * 8;
            CP_ASYNC16(dbase + kk * KSTRB + (e & 7) * 16,
                       vb + (size_t)kk * N_ + s * 64 + c8);
        }
        CP_COMMIT();
    };

    stageB(0, 0);

    for (int s = 0; s < 16; s++) {
        int buf = s & 1;
        if (s < 15) { stageB(s + 1, buf ^ 1); CP_WAIT(1); }
        else        { CP_WAIT(0); }
        __syncthreads();
        unsigned bbase = sbase + (unsigned)buf * BTILEB;
        unsigned lrow = (lid & 15);
        unsigned lcolsel = (lid >> 4);   // 0: n-block np*2, 1: np*2+1
#pragma unroll
        for (int np = 0; np < 4; np++) {
            float c0a = bias_lo, c1a = bias_lo, c2a = bias_hi, c3a = bias_hi;
            float c0b = bias_lo, c1b = bias_lo, c2b = bias_hi, c3b = bias_hi;
            unsigned coladdr = bbase + 16 * (2 * np + lcolsel);
#pragma unroll
            for (int j = 0; j < 12; j++) {
                unsigned b0, b1, b2, b3;
                ldsm_x4_t(b0, b1, b2, b3, coladdr + (16 * j + lrow) * KSTRB);
                mma_fp16(c0a, c1a, c2a, c3a, ah[j][0], ah[j][1], ah[j][2], ah[j][3], b0, b1);
                mma_fp16(c0a, c1a, c2a, c3a, al[j][0], al[j][1], al[j][2], al[j][3], b0, b1);
                mma_fp16(c0b, c1b, c2b, c3b, ah[j][0], ah[j][1], ah[j][2], ah[j][3], b2, b3);
                mma_fp16(c0b, c1b, c2b, c3b, al[j][0], al[j][1], al[j][2], al[j][3], b2, b3);
            }
            int col = n0 + s * 64 + 16 * np + 2 * t;
            float* op0 = out + (size_t)(b * C_ + r0) * N_ + col;
            float* op1 = out + (size_t)(b * C_ + r1) * N_ + col;
            *(float2*)op0       = make_float2(c0a, c1a);
            *(float2*)op1       = make_float2(c2a, c3a);
            *(float2*)(op0 + 8) = make_float2(c0b, c1b);
            *(float2*)(op1 + 8) = make_float2(c2b, c3b);
        }
        __syncthreads();
    }
}

// ---------------------------------------------------------------------------
extern "C" void kernel_launch(void* const* d_in, const int* in_sizes, int n_in,
                              void* d_out, int out_size) {
    const float* x     = (const float*)d_in[0];
    const float* w_qkv = (const float*)d_in[1];
    const float* b_qkv = (const float*)d_in[2];
    const float* temp  = (const float*)d_in[3];
    const float* w_out = (const float*)d_in[4];
    const float* b_out = (const float*)d_in[5];
    float* out = (float*)d_out;

    (void)in_sizes; (void)n_in; (void)out_size;

    static int inited = 0;
    const int conv_smem = 66 * 132 * 4;
    const int comp_smem = (6144 + 32 * 192) * 4;
    if (!inited) {
        cudaFuncSetAttribute(conv_k,     cudaFuncAttributeMaxDynamicSharedMemorySize, conv_smem);
        cudaFuncSetAttribute(gram_k,     cudaFuncAttributeMaxDynamicSharedMemorySize, GRAM_SMEM);
        cudaFuncSetAttribute(compose_k,  cudaFuncAttributeMaxDynamicSharedMemorySize, comp_smem);
        cudaFuncSetAttribute(gemm_out_k, cudaFuncAttributeMaxDynamicSharedMemorySize, GEMM_SMEM);
        inited = 1;
    }

    // 4 launches; profiled launch (idx 3) = gemm_out_k (verify fp16 path).
    conv_k<<<dim3(C_, 2, B_), 256, conv_smem>>>(x, w_qkv, b_qkv);
    gram_k<<<dim3(16, NH_, B_), 128, GRAM_SMEM>>>();
    compose_k<<<dim3(6, B_), 256, comp_smem>>>(temp, w_out);
    gemm_out_k<<<dim3(N_ / 1024, B_), 384, GEMM_SMEM>>>(b_out, out);
}

// round 15
// speedup vs baseline: 3.2605x; 1.0988x over previous
#include <cuda_runtime.h>
#include <cuda_bf16.h>
#include <cuda_fp16.h>

#define B_ 8
#define C_ 192
#define N_ 16384
#define NH_ 6
#define HD_ 32

// Scratch (device globals: allocation-free per harness rules)
__device__ __nv_bfloat16 g_q[B_*C_*N_];
__device__ __nv_bfloat16 g_k[B_*C_*N_];
__device__ __half g_v[B_*C_*N_];
__device__ float g_ssq[2*B_*C_];   // two half-plane partials
__device__ float g_ssk[2*B_*C_];
__device__ float g_G[B_*NH_*HD_*HD_];
__device__ float g_M[B_*C_*C_];

__device__ __forceinline__ unsigned su32(const void* p) {
    unsigned r;
    asm("{ .reg .u64 t; cvta.to.shared.u64 t, %1; cvt.u32.u64 %0, t; }"
        : "=r"(r) : "l"(p));
    return r;
}
// pack (lo=a, hi=b) into one bf16x2 word
__device__ __forceinline__ unsigned bf2(float lo, float hi) {
    unsigned r;
    asm("cvt.rn.bf16x2.f32 %0, %1, %2;" : "=r"(r) : "f"(hi), "f"(lo));
    return r;
}
#define CP_ASYNC16(s, g) asm volatile("cp.async.ca.shared.global [%0], [%1], 16;" :: "r"(s), "l"(g))
#define CP_COMMIT()      asm volatile("cp.async.commit_group;")
#define CP_WAIT(n)       asm volatile("cp.async.wait_group %0;" :: "n"(n))

__device__ __forceinline__ void ldsm_x4(unsigned& r0, unsigned& r1, unsigned& r2,
                                        unsigned& r3, unsigned addr) {
    asm volatile("ldmatrix.sync.aligned.m8n8.x4.shared.b16 {%0,%1,%2,%3}, [%4];"
                 : "=r"(r0), "=r"(r1), "=r"(r2), "=r"(r3) : "r"(addr));
}
__device__ __forceinline__ void ldsm_x2(unsigned& r0, unsigned& r1, unsigned addr) {
    asm volatile("ldmatrix.sync.aligned.m8n8.x2.shared.b16 {%0,%1}, [%2];"
                 : "=r"(r0), "=r"(r1) : "r"(addr));
}
__device__ __forceinline__ void ldsm_x4_t(unsigned& r0, unsigned& r1, unsigned& r2,
                                          unsigned& r3, unsigned addr) {
    asm volatile("ldmatrix.sync.aligned.m8n8.x4.trans.shared.b16 {%0,%1,%2,%3}, [%4];"
                 : "=r"(r0), "=r"(r1), "=r"(r2), "=r"(r3) : "r"(addr));
}
__device__ __forceinline__ void mma_bf16(float& c0, float& c1, float& c2, float& c3,
                                         unsigned a0, unsigned a1, unsigned a2, unsigned a3,
                                         unsigned b0, unsigned b1) {
    asm volatile(
        "mma.sync.aligned.m16n8k16.row.col.f32.bf16.bf16.f32 "
        "{%0,%1,%2,%3}, {%4,%5,%6,%7}, {%8,%9}, {%0,%1,%2,%3};"
        : "+f"(c0), "+f"(c1), "+f"(c2), "+f"(c3)
        : "r"(a0), "r"(a1), "r"(a2), "r"(a3), "r"(b0), "r"(b1));
}
__device__ __forceinline__ void mma_fp16(float& c0, float& c1, float& c2, float& c3,
                                         unsigned a0, unsigned a1, unsigned a2, unsigned a3,
                                         unsigned b0, unsigned b1) {
    asm volatile(
        "mma.sync.aligned.m16n8k16.row.col.f32.f16.f16.f32 "
        "{%0,%1,%2,%3}, {%4,%5,%6,%7}, {%8,%9}, {%0,%1,%2,%3};"
        : "+f"(c0), "+f"(c1), "+f"(c2), "+f"(c3)
        : "r"(a0), "r"(a1), "r"(a2), "r"(a3), "r"(b0), "r"(b1));
}

// ---------------------------------------------------------------------------
// K1: depthwise 3x3 conv, half-plane blocks (instruction-lean).
// q/k -> bf16 (+ssq/ssk partials); v -> fp16.
// ---------------------------------------------------------------------------
__global__ __launch_bounds__(256) void conv_k(const float* __restrict__ x,
                                              const float* __restrict__ w,
                                              const float* __restrict__ bias) {
    const int RS = 132;
    extern __shared__ float tile[];    // [66][132]
    int cin = blockIdx.x, half = blockIdx.y, b = blockIdx.z;
    int tid = threadIdx.x, wid = tid >> 5, lane = tid & 31;
    if (b == 0 && half == 0 && cin < 48) {
        float* Gz = g_G + cin * 1024;
        for (int i = tid; i < 1024; i += 256) Gz[i] = 0.f;
    }
    int r0 = half * 64;
    const float* xp = x + ((size_t)b * C_ + cin) * N_;
    for (int rr = wid; rr < 66; rr += 8) {
        int yy = r0 + rr - 1;
        bool rowok = (unsigned)yy < 128u;
        const float* rp = xp + yy * 128 - 1;
        float* tp = tile + rr * RS;
#pragma unroll
        for (int c = lane; c < 130; c += 32) {
            float v = 0.f;
            if (rowok && c >= 1 && c <= 128) v = rp[c];
            tp[c] = v;
        }
    }
    __syncthreads();

    int o0 = cin * 3;
    float w9[3][9], bs[3];
#pragma unroll
    for (int j = 0; j < 3; j++) {
        int o = o0 + j;
        bs[j] = bias[o];
#pragma unroll
        for (int t = 0; t < 9; t++) w9[j][t] = w[o * 9 + t];
    }
    size_t hoff = (size_t)r0 * 128;

    if (cin < 128) {
        __nv_bfloat16* dst[3];
#pragma unroll
        for (int j = 0; j < 3; j++) {
            int o = o0 + j;
            if (o < C_) dst[j] = g_q + ((size_t)b * C_ + o) * N_ + hoff;
            else        dst[j] = g_k + ((size_t)b * C_ + (o - C_)) * N_ + hoff;
        }
        float ss[3] = {0.f, 0.f, 0.f};
#pragma unroll
        for (int q = 0; q < 8; q++) {
            int p4 = tid + q * 256;
            int r = p4 >> 5, cc = (p4 & 31) << 2;
            const float* trow = tile + r * RS + cc;
            float xr[3][6];
#pragma unroll
            for (int dy = 0; dy < 3; dy++) {
                float4 f = *(const float4*)(trow + dy * RS);
                float2 g2 = *(const float2*)(trow + dy * RS + 4);
                xr[dy][0] = f.x; xr[dy][1] = f.y; xr[dy][2] = f.z;
                xr[dy][3] = f.w; xr[dy][4] = g2.x; xr[dy][5] = g2.y;
            }
#pragma unroll
            for (int j = 0; j < 3; j++) {
                float a[4];
#pragma unroll
                for (int i = 0; i < 4; i++) {
                    float acc = bs[j];
#pragma unroll
                    for (int dy = 0; dy < 3; dy++)
#pragma unroll
                        for (int dx = 0; dx < 3; dx++)
                            acc = fmaf(xr[dy][i + dx], w9[j][dy * 3 + dx], acc);
                    a[i] = acc;
                }
                ss[j] = fmaf(a[0], a[0], fmaf(a[1], a[1],
                         fmaf(a[2], a[2], fmaf(a[3], a[3], ss[j]))));
                uint2 pk = make_uint2(bf2(a[0], a[1]), bf2(a[2], a[3]));
                *(uint2*)(dst[j] + p4 * 4) = pk;
            }
        }
        __shared__ float red[3][8];
#pragma unroll
        for (int j = 0; j < 3; j++) {
            float v = ss[j];
#pragma unroll
            for (int off = 16; off > 0; off >>= 1) v += __shfl_xor_sync(0xffffffffu, v, off);
            if (lane == 0) red[j][wid] = v;
        }
        __syncthreads();
        if (tid < 3) {
            float t = 0.f;
#pragma unroll
            for (int wd = 0; wd < 8; wd++) t += red[tid][wd];
            int o = o0 + tid;
            int part = half * B_ * C_;
            if (o < C_) g_ssq[part + b * C_ + o] = t;
            else        g_ssk[part + b * C_ + (o - C_)] = t;
        }
    } else {
        __half* dst[3];
#pragma unroll
        for (int j = 0; j < 3; j++)
            dst[j] = g_v + ((size_t)b * C_ + (o0 + j - 2 * C_)) * N_ + hoff;
#pragma unroll
        for (int q = 0; q < 8; q++) {
            int p4 = tid + q * 256;
            int r = p4 >> 5, cc = (p4 & 31) << 2;
            const float* trow = tile + r * RS + cc;
            float xr[3][6];
#pragma unroll
            for (int dy = 0; dy < 3; dy++) {
                float4 f = *(const float4*)(trow + dy * RS);
                float2 g2 = *(const float2*)(trow + dy * RS + 4);
                xr[dy][0] = f.x; xr[dy][1] = f.y; xr[dy][2] = f.z;
                xr[dy][3] = f.w; xr[dy][4] = g2.x; xr[dy][5] = g2.y;
            }
#pragma unroll
            for (int j = 0; j < 3; j++) {
                float a[4];
#pragma unroll
                for (int i = 0; i < 4; i++) {
                    float acc = bs[j];
#pragma unroll
                    for (int dy = 0; dy < 3; dy++)
#pragma unroll
                        for (int dx = 0; dx < 3; dx++)
                            acc = fmaf(xr[dy][i + dx], w9[j][dy * 3 + dx], acc);
                    a[i] = acc;
                }
                __half2 h01 = __floats2half2_rn(a[0], a[1]);
                __half2 h23 = __floats2half2_rn(a[2], a[3]);
                uint2 pk = make_uint2(*(unsigned*)&h01, *(unsigned*)&h23);
                *(uint2*)(dst[j] + p4 * 4) = pk;
            }
        }
    }
}

// ---------------------------------------------------------------------------
// K2: gram G[b,h] += q_h @ k_h^T via mma.sync bf16 (m16n8k16) + ldmatrix.
// ---------------------------------------------------------------------------
#define GROW 272
#define GARR (32 * GROW)
#define GBUF (2 * GARR)
#define GRAM_SMEM (2 * GBUF)

__global__ __launch_bounds__(128) void gram_k() {
    extern __shared__ char gsm[];
    unsigned smem_base = su32(gsm);
    int chunk = blockIdx.x, h = blockIdx.y, b = blockIdx.z;
    const __nv_bfloat16* qb = g_q + ((size_t)b * C_ + h * HD_) * N_;
    const __nv_bfloat16* kb = g_k + ((size_t)b * C_ + h * HD_) * N_;
    int tid = threadIdx.x, wid = tid >> 5, lane = tid & 31;
    int n0 = chunk * 1024;

    int mt = wid & 1;
    int nb0 = (wid >> 1) * 2;

    auto stage = [&](int sub, int buf) {
        unsigned dstq = smem_base + buf * GBUF;
        unsigned dstk = dstq + GARR;
        int r = tid >> 4, s16 = tid & 15;
#pragma unroll
        for (int i = 0; i < 4; i++) {
            int row = r + i * 8;
            const __nv_bfloat16* sq = qb + (size_t)row * N_ + n0 + sub * 128 + s16 * 8;
            const __nv_bfloat16* sk = kb + (size_t)row * N_ + n0 + sub * 128 + s16 * 8;
            CP_ASYNC16(dstq + row * GROW + s16 * 16, sq);
            CP_ASYNC16(dstk + row * GROW + s16 * 16, sk);
        }
        CP_COMMIT();
    };

    stage(0, 0);

    float acc[2][4];
#pragma unroll
    for (int nbi = 0; nbi < 2; nbi++)
#pragma unroll
        for (int p = 0; p < 4; p++) acc[nbi][p] = 0.f;

    unsigned a_off = (lane & 15) * GROW + (lane >> 4) * 16;
    unsigned b_off = (lane & 7) * GROW + ((lane >> 3) & 1) * 16;

    for (int sub = 0; sub < 8; sub++) {
        int buf = sub & 1;
        if (sub < 7) { stage(sub + 1, buf ^ 1); CP_WAIT(1); }
        else         { CP_WAIT(0); }
        __syncthreads();
        unsigned qs = smem_base + buf * GBUF + mt * 16 * GROW;
        unsigned ks = smem_base + buf * GBUF + GARR;
#pragma unroll
        for (int ksix = 0; ksix < 8; ksix++) {
            unsigned a0, a1, a2, a3;
            ldsm_x4(a0, a1, a2, a3, qs + a_off + ksix * 32);
#pragma unroll
            for (int nbi = 0; nbi < 2; nbi++) {
                unsigned b0, b1;
                ldsm_x2(b0, b1, ks + (nb0 + nbi) * 8 * GROW + b_off + ksix * 32);
                mma_bf16(acc[nbi][0], acc[nbi][1], acc[nbi][2], acc[nbi][3],
                         a0, a1, a2, a3, b0, b1);
            }
        }
        __syncthreads();
    }

    float* Gp = g_G + ((b * NH_ + h) << 10);
    int row = lane >> 2, colp = 2 * (lane & 3);
#pragma unroll
    for (int nbi = 0; nbi < 2; nbi++) {
        int cbase = (nb0 + nbi) * 8 + colp;
        atomicAdd(&Gp[(mt * 16 + row) * 32 + cbase],         acc[nbi][0]);
        atomicAdd(&Gp[(mt * 16 + row) * 32 + cbase + 1],     acc[nbi][1]);
        atomicAdd(&Gp[(mt * 16 + row + 8) * 32 + cbase],     acc[nbi][2]);
        atomicAdd(&Gp[(mt * 16 + row + 8) * 32 + cbase + 1], acc[nbi][3]);
    }
}

// ---------------------------------------------------------------------------
// K3: softmax + compose M[b] = w_out @ blockdiag(attn heads). grid (6, B).
// ---------------------------------------------------------------------------
__global__ __launch_bounds__(256) void compose_k(const float* __restrict__ temp,
                                                 const float* __restrict__ w_out) {
    extern __shared__ float cs[];
    float* A   = cs;          // [6*32*32]
    float* Wsh = cs + 6144;   // [32*192]
    __shared__ float sinvsh[C_];
    int oc = blockIdx.x, b = blockIdx.y;
    int o0 = oc * 32;
    int tid = threadIdx.x;

    if (tid < C_) {
        float sk = g_ssk[b * C_ + tid] + g_ssk[B_ * C_ + b * C_ + tid];
        sinvsh[tid] = 1.f / fmaxf(sqrtf(sk), 1e-12f);
    }
    for (int i = tid; i < 32 * 192; i += 256) {
        int o = i / 192, c = i - o * 192;
        Wsh[i] = w_out[(o0 + o) * C_ + c];
    }
    __syncthreads();
    if (tid < C_) {
        int h = tid >> 5, cl = tid & 31;
        float sq = g_ssq[b * C_ + tid] + g_ssq[B_ * C_ + b * C_ + tid];
        float nq = fmaxf(sqrtf(sq), 1e-12f);
        float sc = temp[h] / nq;
        const float* Gr = g_G + ((b * NH_ + h) << 10) + cl * HD_;
        const float* si = sinvsh + h * HD_;
        float row[32], mx = -3.4e38f;
#pragma unroll
        for (int d = 0; d < 32; d++) {
            float v = Gr[d] * sc * si[d];
            row[d] = v;
            mx = fmaxf(mx, v);
        }
        float s = 0.f;
#pragma unroll
        for (int d = 0; d < 32; d++) { row[d] = expf(row[d] - mx); s += row[d]; }
        float inv = 1.f / s;
#pragma unroll
        for (int d = 0; d < 32; d++) A[h * 1024 + cl * 32 + d] = row[d] * inv;
    }
    __syncthreads();
    float* Mb = g_M + (size_t)b * C_ * C_ + (size_t)o0 * C_;
    for (int i = tid; i < 32 * 192; i += 256) {
        int o = i / 192, g = i - o * 192;
        int h = g >> 5, d = g & 31;
        const float* wr = Wsh + o * 192 + h * 32;
        const float* Ar = A + h * 1024 + d;
        float acc = 0.f;
#pragma unroll
        for (int cl = 0; cl < 32; cl++) acc = fmaf(wr[cl], Ar[cl * 32], acc);
        Mb[i] = acc;
    }
}

// ---------------------------------------------------------------------------
// K4: out[b] = M[b](192x192) @ v[b](192xN) + b_out via mma.sync fp16
// (m16n8k16, f32 accum). A = M as single fp16 (rel ~2.8e-4, within budget);
// B = v fp16 [192k x 64n-contig] smem tile, fragments via ldmatrix.x4.trans,
// cp.async-staged, double-buffered; 16 stages of n=64.
// ---------------------------------------------------------------------------
#define KSTRB 144                 // bytes per k-row (64 halves + 8 pad)
#define BTILEB (192 * KSTRB)      // bytes per buffer = 27648
#define GEMM_SMEM (2 * BTILEB)    // 55296

__global__ __launch_bounds__(384, 1) void gemm_out_k(const float* __restrict__ b_out,
                                                     float* __restrict__ out) {
    extern __shared__ char Bsm[];
    unsigned sbase = su32(Bsm);
    int tid = threadIdx.x, wid = tid >> 5, lid = tid & 31;
    int b = blockIdx.y;
    int n0 = blockIdx.x * 1024;

    const float* Mg = g_M + (size_t)b * C_ * C_;
    const __half* vb = g_v + (size_t)b * C_ * N_ + n0;

    // ---- A fragments: M rows as fp16 (packed half2), in regs ----
    int g = lid >> 2, t = lid & 3;
    int r0 = 16 * wid + g, r1 = r0 + 8;
    unsigned ah[12][4];
#pragma unroll
    for (int j = 0; j < 12; j++) {
        const float* m0 = Mg + (size_t)r0 * C_ + 16 * j + 2 * t;
        const float* m1 = Mg + (size_t)r1 * C_ + 16 * j + 2 * t;
        __half2 p0 = __floats2half2_rn(m0[0], m0[1]);
        __half2 p1 = __floats2half2_rn(m1[0], m1[1]);
        __half2 p2 = __floats2half2_rn(m0[8], m0[9]);
        __half2 p3 = __floats2half2_rn(m1[8], m1[9]);
        ah[j][0] = *(unsigned*)&p0;
        ah[j][1] = *(unsigned*)&p1;
        ah[j][2] = *(unsigned*)&p2;
        ah[j][3] = *(unsigned*)&p3;
    }
    float bias_lo = b_out[r0], bias_hi = b_out[r1];

    auto stageB = [&](int s, int buf) {
        unsigned dbase = sbase + (unsigned)buf * BTILEB;
#pragma unroll
        for (int i = 0; i < 4; i++) {
            int e = tid + i * 384;
            int kk = e >> 3, c8 = (e & 7) * 8;
            CP_ASYNC16(dbase + kk * KSTRB + (e & 7) * 16,
                       vb + (size_t)kk * N_ + s * 64 + c8);
        }
        CP_COMMIT();
    };

    stageB(0, 0);

    for (int s = 0; s < 16; s++) {
        int buf = s & 1;
        if (s < 15) { stageB(s + 1, buf ^ 1); CP_WAIT(1); }
        else        { CP_WAIT(0); }
        __syncthreads();
        unsigned bbase = sbase + (unsigned)buf * BTILEB;
        unsigned lrow = (lid & 15);
        unsigned lcolsel = (lid >> 4);   // 0: n-block np*2, 1: np*2+1
#pragma unroll
        for (int np = 0; np < 4; np++) {
            float c0a = bias_lo, c1a = bias_lo, c2a = bias_hi, c3a = bias_hi;
            float c0b = bias_lo, c1b = bias_lo, c2b = bias_hi, c3b = bias_hi;
            unsigned coladdr = bbase + 16 * (2 * np + lcolsel);
#pragma unroll
            for (int j = 0; j < 12; j++) {
                unsigned b0, b1, b2, b3;
                ldsm_x4_t(b0, b1, b2, b3, coladdr + (16 * j + lrow) * KSTRB);
                mma_fp16(c0a, c1a, c2a, c3a, ah[j][0], ah[j][1], ah[j][2], ah[j][3], b0, b1);
                mma_fp16(c0b, c1b, c2b, c3b, ah[j][0], ah[j][1], ah[j][2], ah[j][3], b2, b3);
            }
            int col = n0 + s * 64 + 16 * np + 2 * t;
            float* op0 = out + (size_t)(b * C_ + r0) * N_ + col;
            float* op1 = out + (size_t)(b * C_ + r1) * N_ + col;
            *(float2*)op0       = make_float2(c0a, c1a);
            *(float2*)op1       = make_float2(c2a, c3a);
            *(float2*)(op0 + 8) = make_float2(c0b, c1b);
            *(float2*)(op1 + 8) = make_float2(c2b, c3b);
        }
        __syncthreads();
    }
}

// ---------------------------------------------------------------------------
extern "C" void kernel_launch(void* const* d_in, const int* in_sizes, int n_in,
                              void* d_out, int out_size) {
    const float* x     = (const float*)d_in[0];
    const float* w_qkv = (const float*)d_in[1];
    const float* b_qkv = (const float*)d_in[2];
    const float* temp  = (const float*)d_in[3];
    const float* w_out = (const float*)d_in[4];
    const float* b_out = (const float*)d_in[5];
    float* out = (float*)d_out;

    (void)in_sizes; (void)n_in; (void)out_size;

    static int inited = 0;
    const int conv_smem = 66 * 132 * 4;
    const int comp_smem = (6144 + 32 * 192) * 4;
    if (!inited) {
        cudaFuncSetAttribute(conv_k,     cudaFuncAttributeMaxDynamicSharedMemorySize, conv_smem);
        cudaFuncSetAttribute(gram_k,     cudaFuncAttributeMaxDynamicSharedMemorySize, GRAM_SMEM);
        cudaFuncSetAttribute(compose_k,  cudaFuncAttributeMaxDynamicSharedMemorySize, comp_smem);
        cudaFuncSetAttribute(gemm_out_k, cudaFuncAttributeMaxDynamicSharedMemorySize, GEMM_SMEM);
        inited = 1;
    }

    // 4 launches; profiled launch (idx 3) = gemm_out_k (verify single-fp16 A).
    conv_k<<<dim3(C_, 2, B_), 256, conv_smem>>>(x, w_qkv, b_qkv);
    gram_k<<<dim3(16, NH_, B_), 128, GRAM_SMEM>>>();
    compose_k<<<dim3(6, B_), 256, comp_smem>>>(temp, w_out);
    gemm_out_k<<<dim3(N_ / 1024, B_), 384, GEMM_SMEM>>>(b_out, out);
}

// round 16
// speedup vs baseline: 3.2655x; 1.0015x over previous
#include <cuda_runtime.h>
#include <cuda_bf16.h>
#include <cuda_fp16.h>

#define B_ 8
#define C_ 192
#define N_ 16384
#define NH_ 6
#define HD_ 32

// Scratch (device globals: allocation-free per harness rules)
__device__ __nv_bfloat16 g_q[B_*C_*N_];
__device__ __nv_bfloat16 g_k[B_*C_*N_];
__device__ __half g_v[B_*C_*N_];
__device__ float g_ssq[2*B_*C_];   // two half-plane partials
__device__ float g_ssk[2*B_*C_];
__device__ float g_G[B_*NH_*HD_*HD_];
__device__ float g_M[B_*C_*C_];

__device__ __forceinline__ unsigned su32(const void* p) {
    unsigned r;
    asm("{ .reg .u64 t; cvta.to.shared.u64 t, %1; cvt.u32.u64 %0, t; }"
        : "=r"(r) : "l"(p));
    return r;
}
// pack (lo=a, hi=b) into one bf16x2 word
__device__ __forceinline__ unsigned bf2(float lo, float hi) {
    unsigned r;
    asm("cvt.rn.bf16x2.f32 %0, %1, %2;" : "=r"(r) : "f"(hi), "f"(lo));
    return r;
}
#define CP_ASYNC16(s, g) asm volatile("cp.async.ca.shared.global [%0], [%1], 16;" :: "r"(s), "l"(g))
#define CP_COMMIT()      asm volatile("cp.async.commit_group;")
#define CP_WAIT(n)       asm volatile("cp.async.wait_group %0;" :: "n"(n))

__device__ __forceinline__ void ldsm_x4(unsigned& r0, unsigned& r1, unsigned& r2,
                                        unsigned& r3, unsigned addr) {
    asm volatile("ldmatrix.sync.aligned.m8n8.x4.shared.b16 {%0,%1,%2,%3}, [%4];"
                 : "=r"(r0), "=r"(r1), "=r"(r2), "=r"(r3) : "r"(addr));
}
__device__ __forceinline__ void ldsm_x2(unsigned& r0, unsigned& r1, unsigned addr) {
    asm volatile("ldmatrix.sync.aligned.m8n8.x2.shared.b16 {%0,%1}, [%2];"
                 : "=r"(r0), "=r"(r1) : "r"(addr));
}
__device__ __forceinline__ void ldsm_x4_t(unsigned& r0, unsigned& r1, unsigned& r2,
                                          unsigned& r3, unsigned addr) {
    asm volatile("ldmatrix.sync.aligned.m8n8.x4.trans.shared.b16 {%0,%1,%2,%3}, [%4];"
                 : "=r"(r0), "=r"(r1), "=r"(r2), "=r"(r3) : "r"(addr));
}
__device__ __forceinline__ void mma_bf16(float& c0, float& c1, float& c2, float& c3,
                                         unsigned a0, unsigned a1, unsigned a2, unsigned a3,
                                         unsigned b0, unsigned b1) {
    asm volatile(
        "mma.sync.aligned.m16n8k16.row.col.f32.bf16.bf16.f32 "
        "{%0,%1,%2,%3}, {%4,%5,%6,%7}, {%8,%9}, {%0,%1,%2,%3};"
        : "+f"(c0), "+f"(c1), "+f"(c2), "+f"(c3)
        : "r"(a0), "r"(a1), "r"(a2), "r"(a3), "r"(b0), "r"(b1));
}
__device__ __forceinline__ void mma_fp16(float& c0, float& c1, float& c2, float& c3,
                                         unsigned a0, unsigned a1, unsigned a2, unsigned a3,
                                         unsigned b0, unsigned b1) {
    asm volatile(
        "mma.sync.aligned.m16n8k16.row.col.f32.f16.f16.f32 "
        "{%0,%1,%2,%3}, {%4,%5,%6,%7}, {%8,%9}, {%0,%1,%2,%3};"
        : "+f"(c0), "+f"(c1), "+f"(c2), "+f"(c3)
        : "r"(a0), "r"(a1), "r"(a2), "r"(a3), "r"(b0), "r"(b1));
}

// ---------------------------------------------------------------------------
// K1: depthwise 3x3 conv, half-plane blocks (instruction-lean).
// q/k -> bf16 (+ssq/ssk partials); v -> fp16.
// ---------------------------------------------------------------------------
__global__ __launch_bounds__(256) void conv_k(const float* __restrict__ x,
                                              const float* __restrict__ w,
                                              const float* __restrict__ bias) {
    const int RS = 132;
    extern __shared__ float tile[];    // [66][132]
    int cin = blockIdx.x, half = blockIdx.y, b = blockIdx.z;
    int tid = threadIdx.x, wid = tid >> 5, lane = tid & 31;
    if (b == 0 && half == 0 && cin < 48) {
        float* Gz = g_G + cin * 1024;
        for (int i = tid; i < 1024; i += 256) Gz[i] = 0.f;
    }
    int r0 = half * 64;
    const float* xp = x + ((size_t)b * C_ + cin) * N_;
    for (int rr = wid; rr < 66; rr += 8) {
        int yy = r0 + rr - 1;
        bool rowok = (unsigned)yy < 128u;
        const float* rp = xp + yy * 128 - 1;
        float* tp = tile + rr * RS;
#pragma unroll
        for (int c = lane; c < 130; c += 32) {
            float v = 0.f;
            if (rowok && c >= 1 && c <= 128) v = rp[c];
            tp[c] = v;
        }
    }
    __syncthreads();

    int o0 = cin * 3;
    float w9[3][9], bs[3];
#pragma unroll
    for (int j = 0; j < 3; j++) {
        int o = o0 + j;
        bs[j] = bias[o];
#pragma unroll
        for (int t = 0; t < 9; t++) w9[j][t] = w[o * 9 + t];
    }
    size_t hoff = (size_t)r0 * 128;

    if (cin < 128) {
        __nv_bfloat16* dst[3];
#pragma unroll
        for (int j = 0; j < 3; j++) {
            int o = o0 + j;
            if (o < C_) dst[j] = g_q + ((size_t)b * C_ + o) * N_ + hoff;
            else        dst[j] = g_k + ((size_t)b * C_ + (o - C_)) * N_ + hoff;
        }
        float ss[3] = {0.f, 0.f, 0.f};
#pragma unroll
        for (int q = 0; q < 8; q++) {
            int p4 = tid + q * 256;
            int r = p4 >> 5, cc = (p4 & 31) << 2;
            const float* trow = tile + r * RS + cc;
            float xr[3][6];
#pragma unroll
            for (int dy = 0; dy < 3; dy++) {
                float4 f = *(const float4*)(trow + dy * RS);
                float2 g2 = *(const float2*)(trow + dy * RS + 4);
                xr[dy][0] = f.x; xr[dy][1] = f.y; xr[dy][2] = f.z;
                xr[dy][3] = f.w; xr[dy][4] = g2.x; xr[dy][5] = g2.y;
            }
#pragma unroll
            for (int j = 0; j < 3; j++) {
                float a[4];
#pragma unroll
                for (int i = 0; i < 4; i++) {
                    float acc = bs[j];
#pragma unroll
                    for (int dy = 0; dy < 3; dy++)
#pragma unroll
                        for (int dx = 0; dx < 3; dx++)
                            acc = fmaf(xr[dy][i + dx], w9[j][dy * 3 + dx], acc);
                    a[i] = acc;
                }
                ss[j] = fmaf(a[0], a[0], fmaf(a[1], a[1],
                         fmaf(a[2], a[2], fmaf(a[3], a[3], ss[j]))));
                uint2 pk = make_uint2(bf2(a[0], a[1]), bf2(a[2], a[3]));
                *(uint2*)(dst[j] + p4 * 4) = pk;
            }
        }
        __shared__ float red[3][8];
#pragma unroll
        for (int j = 0; j < 3; j++) {
            float v = ss[j];
#pragma unroll
            for (int off = 16; off > 0; off >>= 1) v += __shfl_xor_sync(0xffffffffu, v, off);
            if (lane == 0) red[j][wid] = v;
        }
        __syncthreads();
        if (tid < 3) {
            float t = 0.f;
#pragma unroll
            for (int wd = 0; wd < 8; wd++) t += red[tid][wd];
            int o = o0 + tid;
            int part = half * B_ * C_;
            if (o < C_) g_ssq[part + b * C_ + o] = t;
            else        g_ssk[part + b * C_ + (o - C_)] = t;
        }
    } else {
        __half* dst[3];
#pragma unroll
        for (int j = 0; j < 3; j++)
            dst[j] = g_v + ((size_t)b * C_ + (o0 + j - 2 * C_)) * N_ + hoff;
#pragma unroll
        for (int q = 0; q < 8; q++) {
            int p4 = tid + q * 256;
            int r = p4 >> 5, cc = (p4 & 31) << 2;
            const float* trow = tile + r * RS + cc;
            float xr[3][6];
#pragma unroll
            for (int dy = 0; dy < 3; dy++) {
                float4 f = *(const float4*)(trow + dy * RS);
                float2 g2 = *(const float2*)(trow + dy * RS + 4);
                xr[dy][0] = f.x; xr[dy][1] = f.y; xr[dy][2] = f.z;
                xr[dy][3] = f.w; xr[dy][4] = g2.x; xr[dy][5] = g2.y;
            }
#pragma unroll
            for (int j = 0; j < 3; j++) {
                float a[4];
#pragma unroll
                for (int i = 0; i < 4; i++) {
                    float acc = bs[j];
#pragma unroll
                    for (int dy = 0; dy < 3; dy++)
#pragma unroll
                        for (int dx = 0; dx < 3; dx++)
                            acc = fmaf(xr[dy][i + dx], w9[j][dy * 3 + dx], acc);
                    a[i] = acc;
                }
                __half2 h01 = __floats2half2_rn(a[0], a[1]);
                __half2 h23 = __floats2half2_rn(a[2], a[3]);
                uint2 pk = make_uint2(*(unsigned*)&h01, *(unsigned*)&h23);
                *(uint2*)(dst[j] + p4 * 4) = pk;
            }
        }
    }
}

// ---------------------------------------------------------------------------
// K2: gram G[b,h] += q_h @ k_h^T via mma.sync bf16 (m16n8k16) + ldmatrix.
// ---------------------------------------------------------------------------
#define GROW 272
#define GARR (32 * GROW)
#define GBUF (2 * GARR)
#define GRAM_SMEM (2 * GBUF)

__global__ __launch_bounds__(128) void gram_k() {
    extern __shared__ char gsm[];
    unsigned smem_base = su32(gsm);
    int chunk = blockIdx.x, h = blockIdx.y, b = blockIdx.z;
    const __nv_bfloat16* qb = g_q + ((size_t)b * C_ + h * HD_) * N_;
    const __nv_bfloat16* kb = g_k + ((size_t)b * C_ + h * HD_) * N_;
    int tid = threadIdx.x, wid = tid >> 5, lane = tid & 31;
    int n0 = chunk * 1024;

    int mt = wid & 1;
    int nb0 = (wid >> 1) * 2;

    auto stage = [&](int sub, int buf) {
        unsigned dstq = smem_base + buf * GBUF;
        unsigned dstk = dstq + GARR;
        int r = tid >> 4, s16 = tid & 15;
#pragma unroll
        for (int i = 0; i < 4; i++) {
            int row = r + i * 8;
            const __nv_bfloat16* sq = qb + (size_t)row * N_ + n0 + sub * 128 + s16 * 8;
            const __nv_bfloat16* sk = kb + (size_t)row * N_ + n0 + sub * 128 + s16 * 8;
            CP_ASYNC16(dstq + row * GROW + s16 * 16, sq);
            CP_ASYNC16(dstk + row * GROW + s16 * 16, sk);
        }
        CP_COMMIT();
    };

    stage(0, 0);

    float acc[2][4];
#pragma unroll
    for (int nbi = 0; nbi < 2; nbi++)
#pragma unroll
        for (int p = 0; p < 4; p++) acc[nbi][p] = 0.f;

    unsigned a_off = (lane & 15) * GROW + (lane >> 4) * 16;
    unsigned b_off = (lane & 7) * GROW + ((lane >> 3) & 1) * 16;

    for (int sub = 0; sub < 8; sub++) {
        int buf = sub & 1;
        if (sub < 7) { stage(sub + 1, buf ^ 1); CP_WAIT(1); }
        else         { CP_WAIT(0); }
        __syncthreads();
        unsigned qs = smem_base + buf * GBUF + mt * 16 * GROW;
        unsigned ks = smem_base + buf * GBUF + GARR;
#pragma unroll
        for (int ksix = 0; ksix < 8; ksix++) {
            unsigned a0, a1, a2, a3;
            ldsm_x4(a0, a1, a2, a3, qs + a_off + ksix * 32);
#pragma unroll
            for (int nbi = 0; nbi < 2; nbi++) {
                unsigned b0, b1;
                ldsm_x2(b0, b1, ks + (nb0 + nbi) * 8 * GROW + b_off + ksix * 32);
                mma_bf16(acc[nbi][0], acc[nbi][1], acc[nbi][2], acc[nbi][3],
                         a0, a1, a2, a3, b0, b1);
            }
        }
        __syncthreads();
    }

    float* Gp = g_G + ((b * NH_ + h) << 10);
    int row = lane >> 2, colp = 2 * (lane & 3);
#pragma unroll
    for (int nbi = 0; nbi < 2; nbi++) {
        int cbase = (nb0 + nbi) * 8 + colp;
        atomicAdd(&Gp[(mt * 16 + row) * 32 + cbase],         acc[nbi][0]);
        atomicAdd(&Gp[(mt * 16 + row) * 32 + cbase + 1],     acc[nbi][1]);
        atomicAdd(&Gp[(mt * 16 + row + 8) * 32 + cbase],     acc[nbi][2]);
        atomicAdd(&Gp[(mt * 16 + row + 8) * 32 + cbase + 1], acc[nbi][3]);
    }
}

// ---------------------------------------------------------------------------
// K3: softmax + compose M[b] = w_out @ blockdiag(attn heads). grid (6, B).
// ---------------------------------------------------------------------------
__global__ __launch_bounds__(256) void compose_k(const float* __restrict__ temp,
                                                 const float* __restrict__ w_out) {
    extern __shared__ float cs[];
    float* A   = cs;          // [6*32*32]
    float* Wsh = cs + 6144;   // [32*192]
    __shared__ float sinvsh[C_];
    int oc = blockIdx.x, b = blockIdx.y;
    int o0 = oc * 32;
    int tid = threadIdx.x;

    if (tid < C_) {
        float sk = g_ssk[b * C_ + tid] + g_ssk[B_ * C_ + b * C_ + tid];
        sinvsh[tid] = 1.f / fmaxf(sqrtf(sk), 1e-12f);
    }
    for (int i = tid; i < 32 * 192; i += 256) {
        int o = i / 192, c = i - o * 192;
        Wsh[i] = w_out[(o0 + o) * C_ + c];
    }
    __syncthreads();
    if (tid < C_) {
        int h = tid >> 5, cl = tid & 31;
        float sq = g_ssq[b * C_ + tid] + g_ssq[B_ * C_ + b * C_ + tid];
        float nq = fmaxf(sqrtf(sq), 1e-12f);
        float sc = temp[h] / nq;
        const float* Gr = g_G + ((b * NH_ + h) << 10) + cl * HD_;
        const float* si = sinvsh + h * HD_;
        float row[32], mx = -3.4e38f;
#pragma unroll
        for (int d = 0; d < 32; d++) {
            float v = Gr[d] * sc * si[d];
            row[d] = v;
            mx = fmaxf(mx, v);
        }
        float s = 0.f;
#pragma unroll
        for (int d = 0; d < 32; d++) { row[d] = expf(row[d] - mx); s += row[d]; }
        float inv = 1.f / s;
#pragma unroll
        for (int d = 0; d < 32; d++) A[h * 1024 + cl * 32 + d] = row[d] * inv;
    }
    __syncthreads();
    float* Mb = g_M + (size_t)b * C_ * C_ + (size_t)o0 * C_;
    for (int i = tid; i < 32 * 192; i += 256) {
        int o = i / 192, g = i - o * 192;
        int h = g >> 5, d = g & 31;
        const float* wr = Wsh + o * 192 + h * 32;
        const float* Ar = A + h * 1024 + d;
        float acc = 0.f;
#pragma unroll
        for (int cl = 0; cl < 32; cl++) acc = fmaf(wr[cl], Ar[cl * 32], acc);
        Mb[i] = acc;
    }
}

// ---------------------------------------------------------------------------
// K4: out[b] = M[b](192x192) @ v[b](192xN) + b_out via mma.sync fp16.
// NEW layout: 6 warps x 32 rows (two m16 tiles per warp) -> each B fragment
// feeds 4 mmas (2m x 2n); B-fragment crossbar traffic halves. n-tile 512,
// 8 stages of 64 cols, 2 CTAs/SM (grid 256).
// ---------------------------------------------------------------------------
#define KSTRB 144                 // bytes per k-row (64 halves + 8 pad)
#define BTILEB (192 * KSTRB)      // bytes per buffer = 27648
#define GEMM_SMEM (2 * BTILEB)    // 55296

__global__ __launch_bounds__(192, 2) void gemm_out_k(const float* __restrict__ b_out,
                                                     float* __restrict__ out) {
    extern __shared__ char Bsm[];
    unsigned sbase = su32(Bsm);
    int tid = threadIdx.x, wid = tid >> 5, lid = tid & 31;
    int b = blockIdx.y;
    int n0 = blockIdx.x * 512;

    const float* Mg = g_M + (size_t)b * C_ * C_;
    const __half* vb = g_v + (size_t)b * C_ * N_ + n0;

    // ---- A fragments: warp owns rows 32*wid..32*wid+31 (2 m16 tiles) ----
    int g = lid >> 2, t = lid & 3;
    int rr[2];
    rr[0] = 32 * wid + g;        // m-tile 0 rows: rr[0], rr[0]+8
    rr[1] = 32 * wid + 16 + g;   // m-tile 1 rows: rr[1], rr[1]+8
    unsigned ah[2][12][4];
#pragma unroll
    for (int m = 0; m < 2; m++)
#pragma unroll
        for (int j = 0; j < 12; j++) {
            const float* m0 = Mg + (size_t)rr[m] * C_ + 16 * j + 2 * t;
            const float* m1 = Mg + (size_t)(rr[m] + 8) * C_ + 16 * j + 2 * t;
            __half2 p0 = __floats2half2_rn(m0[0], m0[1]);
            __half2 p1 = __floats2half2_rn(m1[0], m1[1]);
            __half2 p2 = __floats2half2_rn(m0[8], m0[9]);
            __half2 p3 = __floats2half2_rn(m1[8], m1[9]);
            ah[m][j][0] = *(unsigned*)&p0;
            ah[m][j][1] = *(unsigned*)&p1;
            ah[m][j][2] = *(unsigned*)&p2;
            ah[m][j][3] = *(unsigned*)&p3;
        }
    float bias[2][2];
#pragma unroll
    for (int m = 0; m < 2; m++) {
        bias[m][0] = b_out[rr[m]];
        bias[m][1] = b_out[rr[m] + 8];
    }

    auto stageB = [&](int s, int buf) {
        unsigned dbase = sbase + (unsigned)buf * BTILEB;
#pragma unroll
        for (int i = 0; i < 8; i++) {
            int e = tid + i * 192;
            int kk = e >> 3, c8 = (e & 7) * 8;
            CP_ASYNC16(dbase + kk * KSTRB + (e & 7) * 16,
                       vb + (size_t)kk * N_ + s * 64 + c8);
        }
        CP_COMMIT();
    };

    stageB(0, 0);

    for (int s = 0; s < 8; s++) {
        int buf = s & 1;
        if (s < 7) { stageB(s + 1, buf ^ 1); CP_WAIT(1); }
        else       { CP_WAIT(0); }
        __syncthreads();
        unsigned bbase = sbase + (unsigned)buf * BTILEB;
        unsigned lrow = (lid & 15);
        unsigned lcolsel = (lid >> 4);   // 0: n-block np*2, 1: np*2+1
#pragma unroll
        for (int np = 0; np < 4; np++) {
            float ca[2][4], cb[2][4];
#pragma unroll
            for (int m = 0; m < 2; m++) {
                ca[m][0] = bias[m][0]; ca[m][1] = bias[m][0];
                ca[m][2] = bias[m][1]; ca[m][3] = bias[m][1];
                cb[m][0] = bias[m][0]; cb[m][1] = bias[m][0];
                cb[m][2] = bias[m][1]; cb[m][3] = bias[m][1];
            }
            unsigned coladdr = bbase + 16 * (2 * np + lcolsel);
#pragma unroll
            for (int j = 0; j < 12; j++) {
                unsigned b0, b1, b2, b3;
                ldsm_x4_t(b0, b1, b2, b3, coladdr + (16 * j + lrow) * KSTRB);
#pragma unroll
                for (int m = 0; m < 2; m++) {
                    mma_fp16(ca[m][0], ca[m][1], ca[m][2], ca[m][3],
                             ah[m][j][0], ah[m][j][1], ah[m][j][2], ah[m][j][3], b0, b1);
                    mma_fp16(cb[m][0], cb[m][1], cb[m][2], cb[m][3],
                             ah[m][j][0], ah[m][j][1], ah[m][j][2], ah[m][j][3], b2, b3);
                }
            }
            int col = n0 + s * 64 + 16 * np + 2 * t;
#pragma unroll
            for (int m = 0; m < 2; m++) {
                float* op0 = out + (size_t)(b * C_ + rr[m]) * N_ + col;
                float* op1 = out + (size_t)(b * C_ + rr[m] + 8) * N_ + col;
                *(float2*)op0       = make_float2(ca[m][0], ca[m][1]);
                *(float2*)op1       = make_float2(ca[m][2], ca[m][3]);
                *(float2*)(op0 + 8) = make_float2(cb[m][0], cb[m][1]);
                *(float2*)(op1 + 8) = make_float2(cb[m][2], cb[m][3]);
            }
        }
        __syncthreads();
    }
}

// ---------------------------------------------------------------------------
extern "C" void kernel_launch(void* const* d_in, const int* in_sizes, int n_in,
                              void* d_out, int out_size) {
    const float* x     = (const float*)d_in[0];
    const float* w_qkv = (const float*)d_in[1];
    const float* b_qkv = (const float*)d_in[2];
    const float* temp  = (const float*)d_in[3];
    const float* w_out = (const float*)d_in[4];
    const float* b_out = (const float*)d_in[5];
    float* out = (float*)d_out;

    (void)in_sizes; (void)n_in; (void)out_size;

    static int inited = 0;
    const int conv_smem = 66 * 132 * 4;
    const int comp_smem = (6144 + 32 * 192) * 4;
    if (!inited) {
        cudaFuncSetAttribute(conv_k,     cudaFuncAttributeMaxDynamicSharedMemorySize, conv_smem);
        cudaFuncSetAttribute(gram_k,     cudaFuncAttributeMaxDynamicSharedMemorySize, GRAM_SMEM);
        cudaFuncSetAttribute(compose_k,  cudaFuncAttributeMaxDynamicSharedMemorySize, comp_smem);
        cudaFuncSetAttribute(gemm_out_k, cudaFuncAttributeMaxDynamicSharedMemorySize, GEMM_SMEM);
        inited = 1;
    }

    // 4 launches; profiled launch (idx 3) = gemm_out_k (verify 6-warp layout).
    conv_k<<<dim3(C_, 2, B_), 256, conv_smem>>>(x, w_qkv, b_qkv);
    gram_k<<<dim3(16, NH_, B_), 128, GRAM_SMEM>>>();
    compose_k<<<dim3(6, B_), 256, comp_smem>>>(temp, w_out);
    gemm_out_k<<<dim3(N_ / 512, B_), 192, GEMM_SMEM>>>(b_out, out);
}